// round 6
// baseline (speedup 1.0000x reference)
#include <cuda_runtime.h>
#include <cuda_bf16.h>
#include <math.h>
#include <stdint.h>

// Problem constants
#define Bsz   16
#define Tlen  1024
#define Din   8704
#define Rdim  256
#define Hdim  72
#define G3    216     // 3*H
#define TAU   12

typedef unsigned long long u64;

// ---------------- scratch (device globals; no allocation allowed) ----------
__device__ __nv_bfloat16 g_wchi[(size_t)G3 * Din];  // combined weight hi (bf16)
__device__ __nv_bfloat16 g_wclo[(size_t)G3 * Din];  // combined weight lo (bf16)
__device__ float g_bc[G3];                          // combined bias
__device__ float g_xp[(size_t)Bsz * Tlen * G3];     // pre-GRU activations
__device__ float g_q[Bsz * Tlen];                   // per-frame scores

// ---------------- helpers ---------------------------------------------------
__device__ __forceinline__ u64 pk2(float lo, float hi) {
    u64 r;
    asm("mov.b64 %0, {%1, %2};" : "=l"(r) : "f"(lo), "f"(hi));
    return r;
}
__device__ __forceinline__ void upk2(u64 v, float& lo, float& hi) {
    asm("mov.b64 {%0, %1}, %2;" : "=f"(lo), "=f"(hi) : "l"(v));
}
__device__ __forceinline__ u64 fma2(u64 a, u64 b, u64 c) {
    u64 d;
    asm("fma.rn.f32x2 %0, %1, %2, %3;" : "=l"(d) : "l"(a), "l"(b), "l"(c));
    return d;
}
__device__ __forceinline__ float sigf(float v) {
    return __fdividef(1.0f, 1.0f + __expf(-v));
}
__device__ __forceinline__ float tanhfast(float v) {
    return 1.0f - __fdividef(2.0f, __expf(2.0f * v) + 1.0f);
}
// split a,b (fp32) into packed bf16x2 hi + lo:  lower16 <- a, upper16 <- b
__device__ __forceinline__ void bf16split(float a, float b, uint32_t& hp, uint32_t& lp) {
    asm("cvt.rn.bf16x2.f32 %0, %1, %2;" : "=r"(hp) : "f"(b), "f"(a));
    float ha = __uint_as_float(hp << 16);
    float hb = __uint_as_float(hp & 0xffff0000u);
    float ra = a - ha, rb = b - hb;
    asm("cvt.rn.bf16x2.f32 %0, %1, %2;" : "=r"(lp) : "f"(rb), "f"(ra));
}
// m16n8k16 bf16 MMA (sm_80+ PTX, no arch-feature suffix needed)
__device__ __forceinline__ void mma_bf16(float* d, uint32_t a0, uint32_t a1,
                                         uint32_t a2, uint32_t a3,
                                         uint32_t b0, uint32_t b1) {
    asm volatile(
        "mma.sync.aligned.m16n8k16.row.col.f32.bf16.bf16.f32 "
        "{%0,%1,%2,%3}, {%4,%5,%6,%7}, {%8,%9}, {%0,%1,%2,%3};"
        : "+f"(d[0]), "+f"(d[1]), "+f"(d[2]), "+f"(d[3])
        : "r"(a0), "r"(a1), "r"(a2), "r"(a3), "r"(b0), "r"(b1));
}

// ---------------- kernel: combined bias b_c = w_ih @ b_dr + b_ih -----------
__global__ void bc_kernel(const float* __restrict__ w_ih,
                          const float* __restrict__ b_dr,
                          const float* __restrict__ b_ih) {
    int g = threadIdx.x;
    if (g >= G3) return;
    float acc = b_ih[g];
    for (int r = 0; r < Rdim; r++) acc += w_ih[g * Rdim + r] * b_dr[r];
    g_bc[g] = acc;
}

// ---------------- kernel: combined weight, split to bf16 hi/lo -------------
// grid (8704/64, 216/24), block 384
__global__ void __launch_bounds__(384) combine_kernel(const float* __restrict__ w_dr,
                                                      const float* __restrict__ w_ih) {
    __shared__ float sWdr[128][64];
    __shared__ float sWih[24][128];
    const int d0 = blockIdx.x * 64;
    const int g0 = blockIdx.y * 24;
    const int tid = threadIdx.x;
    const int dloc = (tid & 15) * 4;
    const int gloc = tid >> 4;

    float a0 = 0.f, a1 = 0.f, a2 = 0.f, a3 = 0.f;

    for (int r0 = 0; r0 < Rdim; r0 += 128) {
        for (int idx = tid; idx < 128 * 64; idx += 384) {
            int r = idx >> 6, d = idx & 63;
            sWdr[r][d] = w_dr[(size_t)(r0 + r) * Din + d0 + d];
        }
        for (int idx = tid; idx < 24 * 128; idx += 384) {
            int g = idx >> 7, r = idx & 127;
            sWih[g][r] = w_ih[(g0 + g) * Rdim + r0 + r];
        }
        __syncthreads();
        #pragma unroll 4
        for (int r = 0; r < 128; r++) {
            float wi = sWih[gloc][r];
            float4 wd = *reinterpret_cast<const float4*>(&sWdr[r][dloc]);
            a0 = fmaf(wi, wd.x, a0);
            a1 = fmaf(wi, wd.y, a1);
            a2 = fmaf(wi, wd.z, a2);
            a3 = fmaf(wi, wd.w, a3);
        }
        __syncthreads();
    }
    uint32_t h01, l01, h23, l23;
    bf16split(a0, a1, h01, l01);
    bf16split(a2, a3, h23, l23);
    const size_t e = (size_t)(g0 + gloc) * Din + d0 + dloc;
    *reinterpret_cast<uint2*>(reinterpret_cast<char*>(g_wchi) + e * 2) = make_uint2(h01, h23);
    *reinterpret_cast<uint2*>(reinterpret_cast<char*>(g_wclo) + e * 2) = make_uint2(l01, l23);
}

// ---------------- kernel: HMMA GEMM  xp = x @ w_c^T + b_c ------------------
// (round-4 version: measured ~312us)
// Block: M=64 x N=216(pad 224). 8 warps: 2 M-warps x 4 N-warps.
// Warp tile 32x56 (2 m16 frags x 7 n8 frags). KC=32 per chunk, double buffered.
// Split-bf16 3 passes: hi*hi + hi*lo + lo*hi, fp32 accumulation.
#define KC      32
#define NCHUNK  (Din / KC)      // 272
#define A_HI    0
#define A_LO    4096
#define B_HI    8192
#define B_LO    22528
#define STAGE   36864
#define BIAS_OFF 73728
#define GEMM_SMEM (BIAS_OFF + 896)

__global__ void __launch_bounds__(256, 1) gemm_hmma_kernel(const float* __restrict__ x,
                                                           const int* __restrict__ x_len) {
    extern __shared__ __align__(16) char sm[];
    const int tid = threadIdx.x;
    const int m0 = blockIdx.x * 64;
    if ((m0 & (Tlen - 1)) >= x_len[m0 >> 10]) return;   // tile fully beyond x_len

    if (tid < G3) *reinterpret_cast<float*>(sm + BIAS_OFF + tid * 4) = g_bc[tid];

    const int ar = tid >> 1, ah = tid & 1;
    const float* asrc = x + (size_t)(m0 + ar) * Din + ah * 16;
    const uint32_t aBaseSt = (uint32_t)(ah * 2048 + (ar >> 3) * 256 + (ar & 7) * 32);
    const int r0t = tid >> 1, j0t = tid & 1;
    const int t1 = tid + 256;
    const int r1t = t1 >> 1, j1t = t1 & 1;
    const bool hasT1 = (tid < 176);
    const __nv_bfloat16* bsrcH0 = g_wchi + (size_t)r0t * Din + j0t * 16;
    const __nv_bfloat16* bsrcL0 = g_wclo + (size_t)r0t * Din + j0t * 16;
    const __nv_bfloat16* bsrcH1 = g_wchi + (size_t)r1t * Din + j1t * 16;
    const __nv_bfloat16* bsrcL1 = g_wclo + (size_t)r1t * Din + j1t * 16;
    const uint32_t b0BaseSt = (uint32_t)(j0t * 7168 + (r0t >> 3) * 256 + (r0t & 7) * 32);
    const uint32_t b1BaseSt = (uint32_t)(j1t * 7168 + (r1t >> 3) * 256 + (r1t & 7) * 32);

    const int wid = tid >> 5;
    const int lane = tid & 31;
    const int wm = wid >> 2;
    const int wn = wid & 3;

    float acc[2][7][4];
    #pragma unroll
    for (int f = 0; f < 2; f++)
        #pragma unroll
        for (int j = 0; j < 7; j++)
            #pragma unroll
            for (int c = 0; c < 4; c++) acc[f][j][c] = 0.f;

    float4 av[4];
    uint4 bh0, bh1, bl0, bl1, ch0, ch1, cl0, cl1;

    // ---------- prologue ----------
    {
        av[0] = __ldg((const float4*)(asrc + 0));
        av[1] = __ldg((const float4*)(asrc + 4));
        av[2] = __ldg((const float4*)(asrc + 8));
        av[3] = __ldg((const float4*)(asrc + 12));
        bh0 = __ldg((const uint4*)bsrcH0);
        bh1 = __ldg((const uint4*)(bsrcH0 + 8));
        bl0 = __ldg((const uint4*)bsrcL0);
        bl1 = __ldg((const uint4*)(bsrcL0 + 8));
        if (hasT1) {
            ch0 = __ldg((const uint4*)bsrcH1);
            ch1 = __ldg((const uint4*)(bsrcH1 + 8));
            cl0 = __ldg((const uint4*)bsrcL1);
            cl1 = __ldg((const uint4*)(bsrcL1 + 8));
        }
        {
            uint32_t H[8], L[8];
            bf16split(av[0].x, av[0].y, H[0], L[0]);
            bf16split(av[0].z, av[0].w, H[1], L[1]);
            bf16split(av[1].x, av[1].y, H[2], L[2]);
            bf16split(av[1].z, av[1].w, H[3], L[3]);
            bf16split(av[2].x, av[2].y, H[4], L[4]);
            bf16split(av[2].z, av[2].w, H[5], L[5]);
            bf16split(av[3].x, av[3].y, H[6], L[6]);
            bf16split(av[3].z, av[3].w, H[7], L[7]);
            if (tid < 128) {
                char* pa = sm + A_HI + aBaseSt;
                char* pl = sm + A_LO + aBaseSt;
                #pragma unroll
                for (int c = 0; c < 4; c++) {
                    *reinterpret_cast<uint2*>(pa + c * 8) = make_uint2(H[c], H[c + 4]);
                    *reinterpret_cast<uint2*>(pl + c * 8) = make_uint2(L[c], L[c + 4]);
                }
            }
        }
        {
            char* ph = sm + B_HI + b0BaseSt;
            char* pl = sm + B_LO + b0BaseSt;
            *reinterpret_cast<uint2*>(ph + 0)  = make_uint2(bh0.x, bh1.x);
            *reinterpret_cast<uint2*>(ph + 8)  = make_uint2(bh0.y, bh1.y);
            *reinterpret_cast<uint2*>(ph + 16) = make_uint2(bh0.z, bh1.z);
            *reinterpret_cast<uint2*>(ph + 24) = make_uint2(bh0.w, bh1.w);
            *reinterpret_cast<uint2*>(pl + 0)  = make_uint2(bl0.x, bl1.x);
            *reinterpret_cast<uint2*>(pl + 8)  = make_uint2(bl0.y, bl1.y);
            *reinterpret_cast<uint2*>(pl + 16) = make_uint2(bl0.z, bl1.z);
            *reinterpret_cast<uint2*>(pl + 24) = make_uint2(bl0.w, bl1.w);
        }
        if (hasT1) {
            char* ph = sm + B_HI + b1BaseSt;
            char* pl = sm + B_LO + b1BaseSt;
            *reinterpret_cast<uint2*>(ph + 0)  = make_uint2(ch0.x, ch1.x);
            *reinterpret_cast<uint2*>(ph + 8)  = make_uint2(ch0.y, ch1.y);
            *reinterpret_cast<uint2*>(ph + 16) = make_uint2(ch0.z, ch1.z);
            *reinterpret_cast<uint2*>(ph + 24) = make_uint2(ch0.w, ch1.w);
            *reinterpret_cast<uint2*>(pl + 0)  = make_uint2(cl0.x, cl1.x);
            *reinterpret_cast<uint2*>(pl + 8)  = make_uint2(cl0.y, cl1.y);
            *reinterpret_cast<uint2*>(pl + 16) = make_uint2(cl0.z, cl1.z);
            *reinterpret_cast<uint2*>(pl + 24) = make_uint2(cl0.w, cl1.w);
        }
    }
    __syncthreads();

    // ---------- main loop ----------
    for (int ck = 0; ck < NCHUNK; ck++) {
        const int s = ck & 1;
        const bool more = (ck + 1 < NCHUNK);

        if (more) {
            const int koff = (ck + 1) * KC;
            av[0] = __ldg((const float4*)(asrc + koff + 0));
            av[1] = __ldg((const float4*)(asrc + koff + 4));
            av[2] = __ldg((const float4*)(asrc + koff + 8));
            av[3] = __ldg((const float4*)(asrc + koff + 12));
            bh0 = __ldg((const uint4*)(bsrcH0 + koff));
            bh1 = __ldg((const uint4*)(bsrcH0 + koff + 8));
            bl0 = __ldg((const uint4*)(bsrcL0 + koff));
            bl1 = __ldg((const uint4*)(bsrcL0 + koff + 8));
            if (hasT1) {
                ch0 = __ldg((const uint4*)(bsrcH1 + koff));
                ch1 = __ldg((const uint4*)(bsrcH1 + koff + 8));
                cl0 = __ldg((const uint4*)(bsrcL1 + koff));
                cl1 = __ldg((const uint4*)(bsrcL1 + koff + 8));
            }
        }

        const char* stg = sm + s * STAGE;
        #pragma unroll
        for (int kb = 0; kb < 2; kb++) {
            const char* pa = stg + A_HI + kb * 2048 + (wm * 4) * 256 + lane * 8;
            const char* pb = stg + B_HI + kb * 7168 + (wn * 7) * 256 + lane * 8;
            uint2 Ah[4], Al[4], Bh[7], Bl[7];
            #pragma unroll
            for (int i = 0; i < 4; i++) {
                Ah[i] = *reinterpret_cast<const uint2*>(pa + i * 256);
                Al[i] = *reinterpret_cast<const uint2*>(pa + (A_LO - A_HI) + i * 256);
            }
            #pragma unroll
            for (int j = 0; j < 7; j++) {
                Bh[j] = *reinterpret_cast<const uint2*>(pb + j * 256);
                Bl[j] = *reinterpret_cast<const uint2*>(pb + (B_LO - B_HI) + j * 256);
            }
            #pragma unroll
            for (int f = 0; f < 2; f++) {
                const uint32_t ah0 = Ah[2 * f].x, ah1 = Ah[2 * f + 1].x;
                const uint32_t ah2 = Ah[2 * f].y, ah3 = Ah[2 * f + 1].y;
                const uint32_t al0 = Al[2 * f].x, al1 = Al[2 * f + 1].x;
                const uint32_t al2 = Al[2 * f].y, al3 = Al[2 * f + 1].y;
                #pragma unroll
                for (int j = 0; j < 7; j++) {
                    mma_bf16(acc[f][j], ah0, ah1, ah2, ah3, Bh[j].x, Bh[j].y);
                    mma_bf16(acc[f][j], ah0, ah1, ah2, ah3, Bl[j].x, Bl[j].y);
                    mma_bf16(acc[f][j], al0, al1, al2, al3, Bh[j].x, Bh[j].y);
                }
            }
        }

        if (more) {
            char* stn = sm + (s ^ 1) * STAGE;
            {
                uint32_t H[8], L[8];
                bf16split(av[0].x, av[0].y, H[0], L[0]);
                bf16split(av[0].z, av[0].w, H[1], L[1]);
                bf16split(av[1].x, av[1].y, H[2], L[2]);
                bf16split(av[1].z, av[1].w, H[3], L[3]);
                bf16split(av[2].x, av[2].y, H[4], L[4]);
                bf16split(av[2].z, av[2].w, H[5], L[5]);
                bf16split(av[3].x, av[3].y, H[6], L[6]);
                bf16split(av[3].z, av[3].w, H[7], L[7]);
                if (tid < 128) {
                    char* pa = stn + A_HI + aBaseSt;
                    char* pl = stn + A_LO + aBaseSt;
                    #pragma unroll
                    for (int c = 0; c < 4; c++) {
                        *reinterpret_cast<uint2*>(pa + c * 8) = make_uint2(H[c], H[c + 4]);
                        *reinterpret_cast<uint2*>(pl + c * 8) = make_uint2(L[c], L[c + 4]);
                    }
                }
            }
            {
                char* ph = stn + B_HI + b0BaseSt;
                char* pl = stn + B_LO + b0BaseSt;
                *reinterpret_cast<uint2*>(ph + 0)  = make_uint2(bh0.x, bh1.x);
                *reinterpret_cast<uint2*>(ph + 8)  = make_uint2(bh0.y, bh1.y);
                *reinterpret_cast<uint2*>(ph + 16) = make_uint2(bh0.z, bh1.z);
                *reinterpret_cast<uint2*>(ph + 24) = make_uint2(bh0.w, bh1.w);
                *reinterpret_cast<uint2*>(pl + 0)  = make_uint2(bl0.x, bl1.x);
                *reinterpret_cast<uint2*>(pl + 8)  = make_uint2(bl0.y, bl1.y);
                *reinterpret_cast<uint2*>(pl + 16) = make_uint2(bl0.z, bl1.z);
                *reinterpret_cast<uint2*>(pl + 24) = make_uint2(bl0.w, bl1.w);
            }
            if (hasT1) {
                char* ph = stn + B_HI + b1BaseSt;
                char* pl = stn + B_LO + b1BaseSt;
                *reinterpret_cast<uint2*>(ph + 0)  = make_uint2(ch0.x, ch1.x);
                *reinterpret_cast<uint2*>(ph + 8)  = make_uint2(ch0.y, ch1.y);
                *reinterpret_cast<uint2*>(ph + 16) = make_uint2(ch0.z, ch1.z);
                *reinterpret_cast<uint2*>(ph + 24) = make_uint2(ch0.w, ch1.w);
                *reinterpret_cast<uint2*>(pl + 0)  = make_uint2(cl0.x, cl1.x);
                *reinterpret_cast<uint2*>(pl + 8)  = make_uint2(cl0.y, cl1.y);
                *reinterpret_cast<uint2*>(pl + 16) = make_uint2(cl0.z, cl1.z);
                *reinterpret_cast<uint2*>(pl + 24) = make_uint2(cl0.w, cl1.w);
            }
        }
        __syncthreads();
    }

    // ---------- epilogue: acc + bias -> g_xp ----------
    const float* sbias = reinterpret_cast<const float*>(sm + BIAS_OFF);
    #pragma unroll
    for (int f = 0; f < 2; f++) {
        const int r0 = m0 + wm * 32 + f * 16 + (lane >> 2);
        #pragma unroll
        for (int j = 0; j < 7; j++) {
            const int n = wn * 56 + j * 8 + (lane & 3) * 2;
            if (n < G3) {
                const float2 bias = *reinterpret_cast<const float2*>(sbias + n);
                float2 o0 = make_float2(acc[f][j][0] + bias.x, acc[f][j][1] + bias.y);
                float2 o1 = make_float2(acc[f][j][2] + bias.x, acc[f][j][3] + bias.y);
                *reinterpret_cast<float2*>(g_xp + (size_t)r0 * G3 + n) = o0;
                *reinterpret_cast<float2*>(g_xp + (size_t)(r0 + 8) * G3 + n) = o1;
            }
        }
    }
}

// ---------------- kernel: GRU (one block per batch, split-dot) -------------
// 512 threads. Phase 1: threads 0..431 each compute a HALF dot (36 elems,
// 9-deep fma2 chain) of W_hh row `out` against h; partials -> smem.
// Phase 2: threads 0..71 combine partials + gates + h update (self-prefetched
// xp). Warp 15 computes q[t-1] overlapped with phase 1.
__global__ void __launch_bounds__(512) gru_kernel(const float* __restrict__ w_hh,
                                                  const float* __restrict__ b_hh,
                                                  const float* __restrict__ w_reg,
                                                  const float* __restrict__ b_reg,
                                                  const int* __restrict__ x_len) {
    __shared__ __align__(16) float hbuf[2][72];
    __shared__ float ph[432];   // [half*216 + out]

    const int b = blockIdx.x;
    const int tid = threadIdx.x;
    const int L = x_len[b];

    // matvec roles
    int out = -1, half = 0;
    if (tid < 216)      { out = tid;       half = 0; }
    else if (tid < 432) { out = tid - 216; half = 1; }

    u64 wl[18];
    u64 accInit = 0ULL;
    if (out >= 0) {
        const u64* wp = reinterpret_cast<const u64*>(w_hh + out * Hdim + half * 36);
        #pragma unroll
        for (int k = 0; k < 18; k++) wl[k] = wp[k];
        if (half == 0) accInit = pk2(b_hh[out], 0.f);
    }

    // gate-thread x registers
    const float* xpb = g_xp + (size_t)b * Tlen * G3;
    float xr = 0.f, xz = 0.f, xn = 0.f;
    if (tid < 72) {
        xr = xpb[tid];
        xz = xpb[72 + tid];
        xn = xpb[144 + tid];
    }

    // q-warp (warp 15)
    const int qlane = tid - 480;
    float wq0 = 0.f, wq1 = 0.f, wq2 = 0.f;
    if (tid >= 480 && qlane < 24) {
        wq0 = w_reg[3 * qlane];
        wq1 = w_reg[3 * qlane + 1];
        wq2 = w_reg[3 * qlane + 2];
    }
    const float breg = b_reg[0];
    if (tid < 72) hbuf[0][tid] = 0.f;
    __syncthreads();

    int cur = 0;
    for (int t = 0; t < L; t++) {
        // gate threads prefetch next step's x (idle during phase 1)
        float pxr = 0.f, pxz = 0.f, pxn = 0.f;
        if (tid < 72 && t + 1 < Tlen) {
            const float* nb = xpb + (size_t)(t + 1) * G3;
            pxr = __ldg(nb + tid);
            pxz = __ldg(nb + 72 + tid);
            pxn = __ldg(nb + 144 + tid);
        }

        if (out >= 0) {
            const ulonglong2* hp4 =
                reinterpret_cast<const ulonglong2*>(&hbuf[cur][half * 36]);
            u64 a0 = accInit, a1 = 0ULL;
            #pragma unroll
            for (int k = 0; k < 9; k++) {
                ulonglong2 hv = hp4[k];
                a0 = fma2(hv.x, wl[2 * k], a0);
                a1 = fma2(hv.y, wl[2 * k + 1], a1);
            }
            float l0, h0, l1, h1;
            upk2(a0, l0, h0);
            upk2(a1, l1, h1);
            ph[half * 216 + out] = (l0 + h0) + (l1 + h1);
        } else if (tid >= 480 && t > 0) {
            float s = 0.f;
            if (qlane < 24) {
                s = hbuf[cur][3 * qlane] * wq0
                  + hbuf[cur][3 * qlane + 1] * wq1
                  + hbuf[cur][3 * qlane + 2] * wq2;
            }
            s += __shfl_down_sync(0xffffffffu, s, 16);
            s += __shfl_down_sync(0xffffffffu, s, 8);
            s += __shfl_down_sync(0xffffffffu, s, 4);
            s += __shfl_down_sync(0xffffffffu, s, 2);
            s += __shfl_down_sync(0xffffffffu, s, 1);
            if (qlane == 0) g_q[b * Tlen + (t - 1)] = s + breg;
        }
        __syncthreads();

        if (tid < 72) {
            const float hr = ph[tid] + ph[216 + tid];
            const float hz = ph[72 + tid] + ph[216 + 72 + tid];
            const float hn = ph[144 + tid] + ph[216 + 144 + tid];
            const float r = sigf(xr + hr);
            const float z = sigf(xz + hz);
            const float n = tanhfast(xn + r * hn);
            hbuf[cur ^ 1][tid] = (1.0f - z) * n + z * hbuf[cur][tid];
            xr = pxr; xz = pxz; xn = pxn;
        }
        __syncthreads();
        cur ^= 1;
    }

    // final q[L-1]
    if (tid >= 480) {
        float s = 0.f;
        if (qlane < 24) {
            s = hbuf[cur][3 * qlane] * wq0
              + hbuf[cur][3 * qlane + 1] * wq1
              + hbuf[cur][3 * qlane + 2] * wq2;
        }
        s += __shfl_down_sync(0xffffffffu, s, 16);
        s += __shfl_down_sync(0xffffffffu, s, 8);
        s += __shfl_down_sync(0xffffffffu, s, 4);
        s += __shfl_down_sync(0xffffffffu, s, 2);
        s += __shfl_down_sync(0xffffffffu, s, 1);
        if (qlane == 0) g_q[b * Tlen + (L - 1)] = s + breg;
    }
    for (int tt = L + tid; tt < Tlen; tt += 512) g_q[b * Tlen + tt] = 0.f;
}

// ---------------- kernel: SITP pooling + heads -----------------------------
__global__ void __launch_bounds__(256) pool_kernel(const int* __restrict__ x_len,
                                                   const float* nw1, const float* nb1,
                                                   const float* nw2, const float* nb2,
                                                   const float* lw, const float* lb,
                                                   float* __restrict__ out) {
    __shared__ float qs[Tlen];
    __shared__ float ws[Tlen];
    __shared__ float red[256];
    const int b = blockIdx.x;
    const int tid = threadIdx.x;
    const int L = x_len[b];

    for (int i = tid; i < Tlen; i += 256) {
        float qv = g_q[b * Tlen + i];
        qs[i] = qv;
        ws[i] = (i < L) ? expf(-qv) : 0.f;
    }
    __syncthreads();

    float sum = 0.f;
    for (int t = tid; t < Tlen; t += 256) {
        if (t < L) {
            float xmin = qs[t];
            #pragma unroll
            for (int j = 1; j < TAU; j++) {
                int s = t - j;
                if (s >= 0) xmin = fminf(xmin, qs[s]);
            }
            float num = 0.f, den = 0.f;
            #pragma unroll
            for (int j = 0; j < TAU; j++) {
                int s = t + j;
                if (s < Tlen) { num += ws[s] * qs[s]; den += ws[s]; }
            }
            float y = (den > 0.f) ? num / fmaxf(den, 1e-30f) : 0.f;
            sum += 0.5f * y + 0.5f * xmin;
        }
    }
    red[tid] = sum;
    __syncthreads();
    for (int off = 128; off > 0; off >>= 1) {
        if (tid < off) red[tid] += red[tid + off];
        __syncthreads();
    }
    if (tid == 0) {
        float rel = sigf(red[0] / (float)L);
        float mapped = sigf(nw1[0] * rel + nb1[0]) * nw2[0] + nb2[0];
        float aligned = lw[0] * mapped + lb[0];
        out[b] = rel;
        out[Bsz + b] = mapped;
        out[2 * Bsz + b] = aligned;
    }
}

// ---------------- launch ----------------------------------------------------
extern "C" void kernel_launch(void* const* d_in, const int* in_sizes, int n_in,
                              void* d_out, int out_size) {
    const float* x     = (const float*)d_in[0];
    const int*   x_len = (const int*)  d_in[1];
    const float* w_dr  = (const float*)d_in[2];
    const float* b_dr  = (const float*)d_in[3];
    const float* w_ih  = (const float*)d_in[4];
    const float* w_hh  = (const float*)d_in[5];
    const float* b_ih  = (const float*)d_in[6];
    const float* b_hh  = (const float*)d_in[7];
    const float* w_reg = (const float*)d_in[8];
    const float* b_reg = (const float*)d_in[9];
    const float* nw1   = (const float*)d_in[10];
    const float* nb1   = (const float*)d_in[11];
    const float* nw2   = (const float*)d_in[12];
    const float* nb2   = (const float*)d_in[13];
    const float* lw    = (const float*)d_in[14];
    const float* lb    = (const float*)d_in[15];
    float* out = (float*)d_out;

    cudaFuncSetAttribute(gemm_hmma_kernel,
                         cudaFuncAttributeMaxDynamicSharedMemorySize, GEMM_SMEM);

    bc_kernel<<<1, 256>>>(w_ih, b_dr, b_ih);
    combine_kernel<<<dim3(Din / 64, G3 / 24), 384>>>(w_dr, w_ih);
    gemm_hmma_kernel<<<(Bsz * Tlen) / 64, 256, GEMM_SMEM>>>(x, x_len);
    gru_kernel<<<Bsz, 512>>>(w_hh, b_hh, w_reg, b_reg, x_len);
    pool_kernel<<<Bsz, 256>>>(x_len, nw1, nb1, nw2, nb2, lw, lb, out);
}

// round 7
// speedup vs baseline: 1.0133x; 1.0133x over previous
#include <cuda_runtime.h>
#include <cuda_bf16.h>
#include <math.h>
#include <stdint.h>

// Problem constants
#define Bsz   16
#define Tlen  1024
#define Din   8704
#define Rdim  256
#define Hdim  72
#define G3    216     // 3*H
#define TAU   12

typedef unsigned long long u64;

// ---------------- scratch (device globals; no allocation allowed) ----------
__device__ __nv_bfloat16 g_wchi[(size_t)G3 * Din];  // combined weight hi (bf16)
__device__ __nv_bfloat16 g_wclo[(size_t)G3 * Din];  // combined weight lo (bf16)
__device__ float g_bc[G3];                          // combined bias
__device__ float g_xp[(size_t)Bsz * Tlen * G3];     // pre-GRU activations
__device__ float g_q[Bsz * Tlen];                   // per-frame scores

// ---------------- helpers ---------------------------------------------------
__device__ __forceinline__ void upk2(u64 v, float& lo, float& hi) {
    asm("mov.b64 {%0, %1}, %2;" : "=f"(lo), "=f"(hi) : "l"(v));
}
__device__ __forceinline__ u64 fma2(u64 a, u64 b, u64 c) {
    u64 d;
    asm("fma.rn.f32x2 %0, %1, %2, %3;" : "=l"(d) : "l"(a), "l"(b), "l"(c));
    return d;
}
__device__ __forceinline__ float sigf(float v) {
    return __fdividef(1.0f, 1.0f + __expf(-v));
}
__device__ __forceinline__ float tanhfast(float v) {
    return 1.0f - __fdividef(2.0f, __expf(2.0f * v) + 1.0f);
}
// split a,b (fp32) into packed bf16x2 hi + lo:  lower16 <- a, upper16 <- b
__device__ __forceinline__ void bf16split(float a, float b, uint32_t& hp, uint32_t& lp) {
    asm("cvt.rn.bf16x2.f32 %0, %1, %2;" : "=r"(hp) : "f"(b), "f"(a));
    float ha = __uint_as_float(hp << 16);
    float hb = __uint_as_float(hp & 0xffff0000u);
    float ra = a - ha, rb = b - hb;
    asm("cvt.rn.bf16x2.f32 %0, %1, %2;" : "=r"(lp) : "f"(rb), "f"(ra));
}
// m16n8k16 bf16 MMA (sm_80+ PTX, no arch-feature suffix needed)
__device__ __forceinline__ void mma_bf16(float* d, uint32_t a0, uint32_t a1,
                                         uint32_t a2, uint32_t a3,
                                         uint32_t b0, uint32_t b1) {
    asm volatile(
        "mma.sync.aligned.m16n8k16.row.col.f32.bf16.bf16.f32 "
        "{%0,%1,%2,%3}, {%4,%5,%6,%7}, {%8,%9}, {%0,%1,%2,%3};"
        : "+f"(d[0]), "+f"(d[1]), "+f"(d[2]), "+f"(d[3])
        : "r"(a0), "r"(a1), "r"(a2), "r"(a3), "r"(b0), "r"(b1));
}

// ---------------- kernel: combined bias b_c = w_ih @ b_dr + b_ih -----------
__global__ void bc_kernel(const float* __restrict__ w_ih,
                          const float* __restrict__ b_dr,
                          const float* __restrict__ b_ih) {
    int g = threadIdx.x;
    if (g >= G3) return;
    float acc = b_ih[g];
    for (int r = 0; r < Rdim; r++) acc += w_ih[g * Rdim + r] * b_dr[r];
    g_bc[g] = acc;
}

// ---------------- kernel: combined weight, split to bf16 hi/lo -------------
// grid (8704/64, 216/24), block 384
__global__ void __launch_bounds__(384) combine_kernel(const float* __restrict__ w_dr,
                                                      const float* __restrict__ w_ih) {
    __shared__ float sWdr[128][64];
    __shared__ float sWih[24][128];
    const int d0 = blockIdx.x * 64;
    const int g0 = blockIdx.y * 24;
    const int tid = threadIdx.x;
    const int dloc = (tid & 15) * 4;
    const int gloc = tid >> 4;

    float a0 = 0.f, a1 = 0.f, a2 = 0.f, a3 = 0.f;

    for (int r0 = 0; r0 < Rdim; r0 += 128) {
        for (int idx = tid; idx < 128 * 64; idx += 384) {
            int r = idx >> 6, d = idx & 63;
            sWdr[r][d] = w_dr[(size_t)(r0 + r) * Din + d0 + d];
        }
        for (int idx = tid; idx < 24 * 128; idx += 384) {
            int g = idx >> 7, r = idx & 127;
            sWih[g][r] = w_ih[(g0 + g) * Rdim + r0 + r];
        }
        __syncthreads();
        #pragma unroll 4
        for (int r = 0; r < 128; r++) {
            float wi = sWih[gloc][r];
            float4 wd = *reinterpret_cast<const float4*>(&sWdr[r][dloc]);
            a0 = fmaf(wi, wd.x, a0);
            a1 = fmaf(wi, wd.y, a1);
            a2 = fmaf(wi, wd.z, a2);
            a3 = fmaf(wi, wd.w, a3);
        }
        __syncthreads();
    }
    uint32_t h01, l01, h23, l23;
    bf16split(a0, a1, h01, l01);
    bf16split(a2, a3, h23, l23);
    const size_t e = (size_t)(g0 + gloc) * Din + d0 + dloc;
    *reinterpret_cast<uint2*>(reinterpret_cast<char*>(g_wchi) + e * 2) = make_uint2(h01, h23);
    *reinterpret_cast<uint2*>(reinterpret_cast<char*>(g_wclo) + e * 2) = make_uint2(l01, l23);
}

// ---------------- kernel: HMMA GEMM  xp = x @ w_c^T + b_c ------------------
// R4 structure + vectorized STS.128 staging stores + B-task rebalance.
// Block: M=64 x N=216(pad 224). 8 warps: 2 M-warps x 4 N-warps.
// Warp tile 32x56 (2 m16 frags x 7 n8 frags). KC=32 per chunk, double buffered.
// Split-bf16 3 passes: hi*hi + hi*lo + lo*hi, fp32 accumulation.
#define KC      32
#define NCHUNK  (Din / KC)      // 272
#define A_HI    0
#define A_LO    4096
#define B_HI    8192
#define B_LO    22528
#define STAGE   36864
#define BIAS_OFF 73728
#define GEMM_SMEM (BIAS_OFF + 896)

__global__ void __launch_bounds__(256, 1) gemm_hmma_kernel(const float* __restrict__ x,
                                                           const int* __restrict__ x_len) {
    extern __shared__ __align__(16) char sm[];
    const int tid = threadIdx.x;
    const int m0 = blockIdx.x * 64;
    if ((m0 & (Tlen - 1)) >= x_len[m0 >> 10]) return;   // tile fully beyond x_len

    if (tid < G3) *reinterpret_cast<float*>(sm + BIAS_OFF + tid * 4) = g_bc[tid];

    const int ar = tid >> 1, ah = tid & 1;
    const float* asrc = x + (size_t)(m0 + ar) * Din + ah * 16;
    const uint32_t aBaseSt = (uint32_t)(ah * 2048 + (ar >> 3) * 256 + (ar & 7) * 32);
    // B task0: all 256 threads; task1: tid in [80,256) -> tasks 256..431
    const int r0t = tid >> 1, j0t = tid & 1;
    const int t1 = tid + 176;
    const int r1t = t1 >> 1, j1t = t1 & 1;
    const bool hasT1 = (tid >= 80);
    const __nv_bfloat16* bsrcH0 = g_wchi + (size_t)r0t * Din + j0t * 16;
    const __nv_bfloat16* bsrcL0 = g_wclo + (size_t)r0t * Din + j0t * 16;
    const __nv_bfloat16* bsrcH1 = g_wchi + (size_t)r1t * Din + j1t * 16;
    const __nv_bfloat16* bsrcL1 = g_wclo + (size_t)r1t * Din + j1t * 16;
    const uint32_t b0BaseSt = (uint32_t)(j0t * 7168 + (r0t >> 3) * 256 + (r0t & 7) * 32);
    const uint32_t b1BaseSt = (uint32_t)(j1t * 7168 + (r1t >> 3) * 256 + (r1t & 7) * 32);

    const int wid = tid >> 5;
    const int lane = tid & 31;
    const int wm = wid >> 2;
    const int wn = wid & 3;

    float acc[2][7][4];
    #pragma unroll
    for (int f = 0; f < 2; f++)
        #pragma unroll
        for (int j = 0; j < 7; j++)
            #pragma unroll
            for (int c = 0; c < 4; c++) acc[f][j][c] = 0.f;

    float4 av[4];
    uint4 bh0, bh1, bl0, bl1, ch0, ch1, cl0, cl1;

    // store helpers (STS.128 merged)
    #define STORE_A(dst) do {                                                   \
        uint32_t H[8], L[8];                                                    \
        bf16split(av[0].x, av[0].y, H[0], L[0]);                                \
        bf16split(av[0].z, av[0].w, H[1], L[1]);                                \
        bf16split(av[1].x, av[1].y, H[2], L[2]);                                \
        bf16split(av[1].z, av[1].w, H[3], L[3]);                                \
        bf16split(av[2].x, av[2].y, H[4], L[4]);                                \
        bf16split(av[2].z, av[2].w, H[5], L[5]);                                \
        bf16split(av[3].x, av[3].y, H[6], L[6]);                                \
        bf16split(av[3].z, av[3].w, H[7], L[7]);                                \
        if (tid < 128) {                                                        \
            char* pa = (dst) + A_HI + aBaseSt;                                  \
            char* pl = (dst) + A_LO + aBaseSt;                                  \
            *reinterpret_cast<uint4*>(pa)      = make_uint4(H[0], H[4], H[1], H[5]); \
            *reinterpret_cast<uint4*>(pa + 16) = make_uint4(H[2], H[6], H[3], H[7]); \
            *reinterpret_cast<uint4*>(pl)      = make_uint4(L[0], L[4], L[1], L[5]); \
            *reinterpret_cast<uint4*>(pl + 16) = make_uint4(L[2], L[6], L[3], L[7]); \
        }                                                                       \
    } while (0)
    #define STORE_B0(dst) do {                                                  \
        char* ph = (dst) + B_HI + b0BaseSt;                                     \
        char* pl = (dst) + B_LO + b0BaseSt;                                     \
        *reinterpret_cast<uint4*>(ph)      = make_uint4(bh0.x, bh1.x, bh0.y, bh1.y); \
        *reinterpret_cast<uint4*>(ph + 16) = make_uint4(bh0.z, bh1.z, bh0.w, bh1.w); \
        *reinterpret_cast<uint4*>(pl)      = make_uint4(bl0.x, bl1.x, bl0.y, bl1.y); \
        *reinterpret_cast<uint4*>(pl + 16) = make_uint4(bl0.z, bl1.z, bl0.w, bl1.w); \
    } while (0)
    #define STORE_B1(dst) do {                                                  \
        char* ph = (dst) + B_HI + b1BaseSt;                                     \
        char* pl = (dst) + B_LO + b1BaseSt;                                     \
        *reinterpret_cast<uint4*>(ph)      = make_uint4(ch0.x, ch1.x, ch0.y, ch1.y); \
        *reinterpret_cast<uint4*>(ph + 16) = make_uint4(ch0.z, ch1.z, ch0.w, ch1.w); \
        *reinterpret_cast<uint4*>(pl)      = make_uint4(cl0.x, cl1.x, cl0.y, cl1.y); \
        *reinterpret_cast<uint4*>(pl + 16) = make_uint4(cl0.z, cl1.z, cl0.w, cl1.w); \
    } while (0)

    // ---------- prologue ----------
    {
        av[0] = __ldg((const float4*)(asrc + 0));
        av[1] = __ldg((const float4*)(asrc + 4));
        av[2] = __ldg((const float4*)(asrc + 8));
        av[3] = __ldg((const float4*)(asrc + 12));
        bh0 = __ldg((const uint4*)bsrcH0);
        bh1 = __ldg((const uint4*)(bsrcH0 + 8));
        bl0 = __ldg((const uint4*)bsrcL0);
        bl1 = __ldg((const uint4*)(bsrcL0 + 8));
        if (hasT1) {
            ch0 = __ldg((const uint4*)bsrcH1);
            ch1 = __ldg((const uint4*)(bsrcH1 + 8));
            cl0 = __ldg((const uint4*)bsrcL1);
            cl1 = __ldg((const uint4*)(bsrcL1 + 8));
        }
        STORE_A(sm);
        STORE_B0(sm);
        if (hasT1) STORE_B1(sm);
    }
    __syncthreads();

    // ---------- main loop ----------
    for (int ck = 0; ck < NCHUNK; ck++) {
        const int s = ck & 1;
        const bool more = (ck + 1 < NCHUNK);

        if (more) {
            const int koff = (ck + 1) * KC;
            av[0] = __ldg((const float4*)(asrc + koff + 0));
            av[1] = __ldg((const float4*)(asrc + koff + 4));
            av[2] = __ldg((const float4*)(asrc + koff + 8));
            av[3] = __ldg((const float4*)(asrc + koff + 12));
            bh0 = __ldg((const uint4*)(bsrcH0 + koff));
            bh1 = __ldg((const uint4*)(bsrcH0 + koff + 8));
            bl0 = __ldg((const uint4*)(bsrcL0 + koff));
            bl1 = __ldg((const uint4*)(bsrcL0 + koff + 8));
            if (hasT1) {
                ch0 = __ldg((const uint4*)(bsrcH1 + koff));
                ch1 = __ldg((const uint4*)(bsrcH1 + koff + 8));
                cl0 = __ldg((const uint4*)(bsrcL1 + koff));
                cl1 = __ldg((const uint4*)(bsrcL1 + koff + 8));
            }
        }

        const char* stg = sm + s * STAGE;
        #pragma unroll
        for (int kb = 0; kb < 2; kb++) {
            const char* pa = stg + A_HI + kb * 2048 + (wm * 4) * 256 + lane * 8;
            const char* pb = stg + B_HI + kb * 7168 + (wn * 7) * 256 + lane * 8;
            uint2 Ah[4], Al[4], Bh[7], Bl[7];
            #pragma unroll
            for (int i = 0; i < 4; i++) {
                Ah[i] = *reinterpret_cast<const uint2*>(pa + i * 256);
                Al[i] = *reinterpret_cast<const uint2*>(pa + (A_LO - A_HI) + i * 256);
            }
            #pragma unroll
            for (int j = 0; j < 7; j++) {
                Bh[j] = *reinterpret_cast<const uint2*>(pb + j * 256);
                Bl[j] = *reinterpret_cast<const uint2*>(pb + (B_LO - B_HI) + j * 256);
            }
            #pragma unroll
            for (int f = 0; f < 2; f++) {
                const uint32_t ah0 = Ah[2 * f].x, ah1 = Ah[2 * f + 1].x;
                const uint32_t ah2 = Ah[2 * f].y, ah3 = Ah[2 * f + 1].y;
                const uint32_t al0 = Al[2 * f].x, al1 = Al[2 * f + 1].x;
                const uint32_t al2 = Al[2 * f].y, al3 = Al[2 * f + 1].y;
                #pragma unroll
                for (int j = 0; j < 7; j++) {
                    mma_bf16(acc[f][j], ah0, ah1, ah2, ah3, Bh[j].x, Bh[j].y);
                    mma_bf16(acc[f][j], ah0, ah1, ah2, ah3, Bl[j].x, Bl[j].y);
                    mma_bf16(acc[f][j], al0, al1, al2, al3, Bh[j].x, Bh[j].y);
                }
            }
        }

        if (more) {
            char* stn = sm + (s ^ 1) * STAGE;
            STORE_A(stn);
            STORE_B0(stn);
            if (hasT1) STORE_B1(stn);
        }
        __syncthreads();
    }

    // ---------- epilogue: acc + bias -> g_xp ----------
    const float* sbias = reinterpret_cast<const float*>(sm + BIAS_OFF);
    #pragma unroll
    for (int f = 0; f < 2; f++) {
        const int r0 = m0 + wm * 32 + f * 16 + (lane >> 2);
        #pragma unroll
        for (int j = 0; j < 7; j++) {
            const int n = wn * 56 + j * 8 + (lane & 3) * 2;
            if (n < G3) {
                const float2 bias = *reinterpret_cast<const float2*>(sbias + n);
                float2 o0 = make_float2(acc[f][j][0] + bias.x, acc[f][j][1] + bias.y);
                float2 o1 = make_float2(acc[f][j][2] + bias.x, acc[f][j][3] + bias.y);
                *reinterpret_cast<float2*>(g_xp + (size_t)r0 * G3 + n) = o0;
                *reinterpret_cast<float2*>(g_xp + (size_t)(r0 + 8) * G3 + n) = o1;
            }
        }
    }
}

// ---------------- kernel: GRU (one block per batch, sequential in T) -------
// Proven 515us version (round 2/5): 256 threads, g<216 matvec (f32x2),
// threads 0..71 gates, warp 7 computes q[t-1] overlapped with the matvec.
__global__ void __launch_bounds__(256) gru_kernel(const float* __restrict__ w_hh,
                                                  const float* __restrict__ b_hh,
                                                  const float* __restrict__ w_reg,
                                                  const float* __restrict__ b_reg,
                                                  const int* __restrict__ x_len) {
    __shared__ __align__(16) float hbuf[2][72];
    __shared__ float pre[144];
    __shared__ float hpn[72];
    __shared__ float xnn[72];

    const int b = blockIdx.x;
    const int g = threadIdx.x;
    const int L = x_len[b];

    u64 wl[36];
    float bh = 0.f;
    if (g < G3) {
        bh = b_hh[g];
        const u64* wp = reinterpret_cast<const u64*>(w_hh + g * Hdim);
        #pragma unroll
        for (int k = 0; k < 36; k++) wl[k] = wp[k];
    }
    const int lane = g - 224;
    float wq0 = 0.f, wq1 = 0.f, wq2 = 0.f;
    if (g >= 224 && lane < 24) {
        wq0 = w_reg[3 * lane];
        wq1 = w_reg[3 * lane + 1];
        wq2 = w_reg[3 * lane + 2];
    }
    const float breg = b_reg[0];
    if (g < 72) hbuf[0][g] = 0.f;
    __syncthreads();

    const float* xpb = g_xp + (size_t)b * Tlen * G3;
    float xcur = (g < G3) ? xpb[g] : 0.f;
    int cur = 0;

    for (int t = 0; t < L; t++) {
        float xnxt = 0.f;
        if (g < G3 && t + 1 < Tlen) xnxt = __ldg(xpb + (size_t)(t + 1) * G3 + g);

        if (g < G3) {
            const ulonglong2* hp4 = reinterpret_cast<const ulonglong2*>(hbuf[cur]);
            u64 a0 = 0ULL, a1 = 0ULL, a2 = 0ULL, a3 = 0ULL;
            #pragma unroll
            for (int k = 0; k < 18; k += 2) {
                ulonglong2 h0 = hp4[k];
                ulonglong2 h1 = hp4[k + 1];
                a0 = fma2(h0.x, wl[2 * k], a0);
                a1 = fma2(h0.y, wl[2 * k + 1], a1);
                a2 = fma2(h1.x, wl[2 * k + 2], a2);
                a3 = fma2(h1.y, wl[2 * k + 3], a3);
            }
            float l0, h0f, l1, h1f, l2, h2f, l3, h3f;
            upk2(a0, l0, h0f); upk2(a1, l1, h1f);
            upk2(a2, l2, h2f); upk2(a3, l3, h3f);
            float hp = bh + ((l0 + h0f) + (l1 + h1f)) + ((l2 + h2f) + (l3 + h3f));
            if (g < 144) {
                pre[g] = xcur + hp;
            } else {
                hpn[g - 144] = hp;
                xnn[g - 144] = xcur;
            }
        } else if (g >= 224 && t > 0) {
            float s = 0.f;
            if (lane < 24) {
                s = hbuf[cur][3 * lane] * wq0
                  + hbuf[cur][3 * lane + 1] * wq1
                  + hbuf[cur][3 * lane + 2] * wq2;
            }
            s += __shfl_down_sync(0xffffffffu, s, 16);
            s += __shfl_down_sync(0xffffffffu, s, 8);
            s += __shfl_down_sync(0xffffffffu, s, 4);
            s += __shfl_down_sync(0xffffffffu, s, 2);
            s += __shfl_down_sync(0xffffffffu, s, 1);
            if (lane == 0) g_q[b * Tlen + (t - 1)] = s + breg;
        }
        __syncthreads();

        if (g < 72) {
            float r = sigf(pre[g]);
            float z = sigf(pre[72 + g]);
            float n = tanhfast(xnn[g] + r * hpn[g]);
            hbuf[cur ^ 1][g] = (1.0f - z) * n + z * hbuf[cur][g];
        }
        __syncthreads();

        cur ^= 1;
        xcur = xnxt;
    }

    if (g >= 224) {
        float s = 0.f;
        if (lane < 24) {
            s = hbuf[cur][3 * lane] * wq0
              + hbuf[cur][3 * lane + 1] * wq1
              + hbuf[cur][3 * lane + 2] * wq2;
        }
        s += __shfl_down_sync(0xffffffffu, s, 16);
        s += __shfl_down_sync(0xffffffffu, s, 8);
        s += __shfl_down_sync(0xffffffffu, s, 4);
        s += __shfl_down_sync(0xffffffffu, s, 2);
        s += __shfl_down_sync(0xffffffffu, s, 1);
        if (lane == 0) g_q[b * Tlen + (L - 1)] = s + breg;
    }
    for (int tt = L + g; tt < Tlen; tt += 256) g_q[b * Tlen + tt] = 0.f;
}

// ---------------- kernel: SITP pooling + heads -----------------------------
__global__ void __launch_bounds__(256) pool_kernel(const int* __restrict__ x_len,
                                                   const float* nw1, const float* nb1,
                                                   const float* nw2, const float* nb2,
                                                   const float* lw, const float* lb,
                                                   float* __restrict__ out) {
    __shared__ float qs[Tlen];
    __shared__ float ws[Tlen];
    __shared__ float red[256];
    const int b = blockIdx.x;
    const int tid = threadIdx.x;
    const int L = x_len[b];

    for (int i = tid; i < Tlen; i += 256) {
        float qv = g_q[b * Tlen + i];
        qs[i] = qv;
        ws[i] = (i < L) ? expf(-qv) : 0.f;
    }
    __syncthreads();

    float sum = 0.f;
    for (int t = tid; t < Tlen; t += 256) {
        if (t < L) {
            float xmin = qs[t];
            #pragma unroll
            for (int j = 1; j < TAU; j++) {
                int s = t - j;
                if (s >= 0) xmin = fminf(xmin, qs[s]);
            }
            float num = 0.f, den = 0.f;
            #pragma unroll
            for (int j = 0; j < TAU; j++) {
                int s = t + j;
                if (s < Tlen) { num += ws[s] * qs[s]; den += ws[s]; }
            }
            float y = (den > 0.f) ? num / fmaxf(den, 1e-30f) : 0.f;
            sum += 0.5f * y + 0.5f * xmin;
        }
    }
    red[tid] = sum;
    __syncthreads();
    for (int off = 128; off > 0; off >>= 1) {
        if (tid < off) red[tid] += red[tid + off];
        __syncthreads();
    }
    if (tid == 0) {
        float rel = sigf(red[0] / (float)L);
        float mapped = sigf(nw1[0] * rel + nb1[0]) * nw2[0] + nb2[0];
        float aligned = lw[0] * mapped + lb[0];
        out[b] = rel;
        out[Bsz + b] = mapped;
        out[2 * Bsz + b] = aligned;
    }
}

// ---------------- launch ----------------------------------------------------
extern "C" void kernel_launch(void* const* d_in, const int* in_sizes, int n_in,
                              void* d_out, int out_size) {
    const float* x     = (const float*)d_in[0];
    const int*   x_len = (const int*)  d_in[1];
    const float* w_dr  = (const float*)d_in[2];
    const float* b_dr  = (const float*)d_in[3];
    const float* w_ih  = (const float*)d_in[4];
    const float* w_hh  = (const float*)d_in[5];
    const float* b_ih  = (const float*)d_in[6];
    const float* b_hh  = (const float*)d_in[7];
    const float* w_reg = (const float*)d_in[8];
    const float* b_reg = (const float*)d_in[9];
    const float* nw1   = (const float*)d_in[10];
    const float* nb1   = (const float*)d_in[11];
    const float* nw2   = (const float*)d_in[12];
    const float* nb2   = (const float*)d_in[13];
    const float* lw    = (const float*)d_in[14];
    const float* lb    = (const float*)d_in[15];
    float* out = (float*)d_out;

    cudaFuncSetAttribute(gemm_hmma_kernel,
                         cudaFuncAttributeMaxDynamicSharedMemorySize, GEMM_SMEM);

    bc_kernel<<<1, 256>>>(w_ih, b_dr, b_ih);
    combine_kernel<<<dim3(Din / 64, G3 / 24), 384>>>(w_dr, w_ih);
    gemm_hmma_kernel<<<(Bsz * Tlen) / 64, 256, GEMM_SMEM>>>(x, x_len);
    gru_kernel<<<Bsz, 256>>>(w_hh, b_hh, w_reg, b_reg, x_len);
    pool_kernel<<<Bsz, 256>>>(x_len, nw1, nb1, nw2, nb2, lw, lb, out);
}

// round 8
// speedup vs baseline: 1.0138x; 1.0006x over previous
#include <cuda_runtime.h>
#include <cuda_bf16.h>
#include <math.h>
#include <stdint.h>

// Problem constants
#define Bsz   16
#define Tlen  1024
#define Din   8704
#define Rdim  256
#define Hdim  72
#define G3    216     // 3*H
#define TAU   12

typedef unsigned long long u64;

// ---------------- scratch (device globals; no allocation allowed) ----------
__device__ __nv_bfloat16 g_wchi[(size_t)G3 * Din];  // combined weight hi (bf16)
__device__ __nv_bfloat16 g_wclo[(size_t)G3 * Din];  // combined weight lo (bf16)
__device__ float g_bc[G3];                          // combined bias
__device__ float g_xp[(size_t)Bsz * Tlen * G3];     // pre-GRU activations
__device__ float g_q[Bsz * Tlen];                   // per-frame scores

// ---------------- helpers ---------------------------------------------------
__device__ __forceinline__ void upk2(u64 v, float& lo, float& hi) {
    asm("mov.b64 {%0, %1}, %2;" : "=f"(lo), "=f"(hi) : "l"(v));
}
__device__ __forceinline__ u64 fma2(u64 a, u64 b, u64 c) {
    u64 d;
    asm("fma.rn.f32x2 %0, %1, %2, %3;" : "=l"(d) : "l"(a), "l"(b), "l"(c));
    return d;
}
__device__ __forceinline__ float sigf(float v) {
    return __fdividef(1.0f, 1.0f + __expf(-v));
}
__device__ __forceinline__ float tanhfast(float v) {
    return 1.0f - __fdividef(2.0f, __expf(2.0f * v) + 1.0f);
}
// split a,b (fp32) into packed bf16x2 hi + lo:  lower16 <- a, upper16 <- b
__device__ __forceinline__ void bf16split(float a, float b, uint32_t& hp, uint32_t& lp) {
    asm("cvt.rn.bf16x2.f32 %0, %1, %2;" : "=r"(hp) : "f"(b), "f"(a));
    float ha = __uint_as_float(hp << 16);
    float hb = __uint_as_float(hp & 0xffff0000u);
    float ra = a - ha, rb = b - hb;
    asm("cvt.rn.bf16x2.f32 %0, %1, %2;" : "=r"(lp) : "f"(rb), "f"(ra));
}
// m16n8k16 bf16 MMA (sm_80+ PTX, no arch-feature suffix needed)
__device__ __forceinline__ void mma_bf16(float* d, uint32_t a0, uint32_t a1,
                                         uint32_t a2, uint32_t a3,
                                         uint32_t b0, uint32_t b1) {
    asm volatile(
        "mma.sync.aligned.m16n8k16.row.col.f32.bf16.bf16.f32 "
        "{%0,%1,%2,%3}, {%4,%5,%6,%7}, {%8,%9}, {%0,%1,%2,%3};"
        : "+f"(d[0]), "+f"(d[1]), "+f"(d[2]), "+f"(d[3])
        : "r"(a0), "r"(a1), "r"(a2), "r"(a3), "r"(b0), "r"(b1));
}

// ---------------- kernel: combined bias b_c = w_ih @ b_dr + b_ih -----------
__global__ void bc_kernel(const float* __restrict__ w_ih,
                          const float* __restrict__ b_dr,
                          const float* __restrict__ b_ih) {
    int g = threadIdx.x;
    if (g >= G3) return;
    float acc = b_ih[g];
    for (int r = 0; r < Rdim; r++) acc += w_ih[g * Rdim + r] * b_dr[r];
    g_bc[g] = acc;
}

// ---------------- kernel: combined weight, split to bf16 hi/lo -------------
// grid (8704/64, 216/24), block 384
__global__ void __launch_bounds__(384) combine_kernel(const float* __restrict__ w_dr,
                                                      const float* __restrict__ w_ih) {
    __shared__ float sWdr[128][64];
    __shared__ float sWih[24][128];
    const int d0 = blockIdx.x * 64;
    const int g0 = blockIdx.y * 24;
    const int tid = threadIdx.x;
    const int dloc = (tid & 15) * 4;
    const int gloc = tid >> 4;

    float a0 = 0.f, a1 = 0.f, a2 = 0.f, a3 = 0.f;

    for (int r0 = 0; r0 < Rdim; r0 += 128) {
        for (int idx = tid; idx < 128 * 64; idx += 384) {
            int r = idx >> 6, d = idx & 63;
            sWdr[r][d] = w_dr[(size_t)(r0 + r) * Din + d0 + d];
        }
        for (int idx = tid; idx < 24 * 128; idx += 384) {
            int g = idx >> 7, r = idx & 127;
            sWih[g][r] = w_ih[(g0 + g) * Rdim + r0 + r];
        }
        __syncthreads();
        #pragma unroll 4
        for (int r = 0; r < 128; r++) {
            float wi = sWih[gloc][r];
            float4 wd = *reinterpret_cast<const float4*>(&sWdr[r][dloc]);
            a0 = fmaf(wi, wd.x, a0);
            a1 = fmaf(wi, wd.y, a1);
            a2 = fmaf(wi, wd.z, a2);
            a3 = fmaf(wi, wd.w, a3);
        }
        __syncthreads();
    }
    uint32_t h01, l01, h23, l23;
    bf16split(a0, a1, h01, l01);
    bf16split(a2, a3, h23, l23);
    const size_t e = (size_t)(g0 + gloc) * Din + d0 + dloc;
    *reinterpret_cast<uint2*>(reinterpret_cast<char*>(g_wchi) + e * 2) = make_uint2(h01, h23);
    *reinterpret_cast<uint2*>(reinterpret_cast<char*>(g_wclo) + e * 2) = make_uint2(l01, l23);
}

// ---------------- kernel: HMMA GEMM  xp = x @ w_c^T + b_c ------------------
// ROUND-4 VERSION VERBATIM (measured ~300us).
// Block: M=64 x N=216(pad 224). 8 warps: 2 M-warps x 4 N-warps.
// Warp tile 32x56 (2 m16 frags x 7 n8 frags). KC=32 per chunk, double buffered.
// Split-bf16 3 passes: hi*hi + hi*lo + lo*hi, fp32 accumulation.
#define KC      32
#define NCHUNK  (Din / KC)      // 272
#define A_HI    0
#define A_LO    4096
#define B_HI    8192
#define B_LO    22528
#define STAGE   36864
#define BIAS_OFF 73728
#define GEMM_SMEM (BIAS_OFF + 896)

__global__ void __launch_bounds__(256, 1) gemm_hmma_kernel(const float* __restrict__ x,
                                                           const int* __restrict__ x_len) {
    extern __shared__ __align__(16) char sm[];
    const int tid = threadIdx.x;
    const int m0 = blockIdx.x * 64;
    if ((m0 & (Tlen - 1)) >= x_len[m0 >> 10]) return;   // tile fully beyond x_len

    if (tid < G3) *reinterpret_cast<float*>(sm + BIAS_OFF + tid * 4) = g_bc[tid];

    const int ar = tid >> 1, ah = tid & 1;
    const float* asrc = x + (size_t)(m0 + ar) * Din + ah * 16;
    const uint32_t aBaseSt = (uint32_t)(ah * 2048 + (ar >> 3) * 256 + (ar & 7) * 32);
    const int r0t = tid >> 1, j0t = tid & 1;
    const int t1 = tid + 256;
    const int r1t = t1 >> 1, j1t = t1 & 1;
    const bool hasT1 = (tid < 176);
    const __nv_bfloat16* bsrcH0 = g_wchi + (size_t)r0t * Din + j0t * 16;
    const __nv_bfloat16* bsrcL0 = g_wclo + (size_t)r0t * Din + j0t * 16;
    const __nv_bfloat16* bsrcH1 = g_wchi + (size_t)r1t * Din + j1t * 16;
    const __nv_bfloat16* bsrcL1 = g_wclo + (size_t)r1t * Din + j1t * 16;
    const uint32_t b0BaseSt = (uint32_t)(j0t * 7168 + (r0t >> 3) * 256 + (r0t & 7) * 32);
    const uint32_t b1BaseSt = (uint32_t)(j1t * 7168 + (r1t >> 3) * 256 + (r1t & 7) * 32);

    const int wid = tid >> 5;
    const int lane = tid & 31;
    const int wm = wid >> 2;
    const int wn = wid & 3;

    float acc[2][7][4];
    #pragma unroll
    for (int f = 0; f < 2; f++)
        #pragma unroll
        for (int j = 0; j < 7; j++)
            #pragma unroll
            for (int c = 0; c < 4; c++) acc[f][j][c] = 0.f;

    float4 av[4];
    uint4 bh0, bh1, bl0, bl1, ch0, ch1, cl0, cl1;

    // ---------- prologue ----------
    {
        av[0] = __ldg((const float4*)(asrc + 0));
        av[1] = __ldg((const float4*)(asrc + 4));
        av[2] = __ldg((const float4*)(asrc + 8));
        av[3] = __ldg((const float4*)(asrc + 12));
        bh0 = __ldg((const uint4*)bsrcH0);
        bh1 = __ldg((const uint4*)(bsrcH0 + 8));
        bl0 = __ldg((const uint4*)bsrcL0);
        bl1 = __ldg((const uint4*)(bsrcL0 + 8));
        if (hasT1) {
            ch0 = __ldg((const uint4*)bsrcH1);
            ch1 = __ldg((const uint4*)(bsrcH1 + 8));
            cl0 = __ldg((const uint4*)bsrcL1);
            cl1 = __ldg((const uint4*)(bsrcL1 + 8));
        }
        {
            uint32_t H[8], L[8];
            bf16split(av[0].x, av[0].y, H[0], L[0]);
            bf16split(av[0].z, av[0].w, H[1], L[1]);
            bf16split(av[1].x, av[1].y, H[2], L[2]);
            bf16split(av[1].z, av[1].w, H[3], L[3]);
            bf16split(av[2].x, av[2].y, H[4], L[4]);
            bf16split(av[2].z, av[2].w, H[5], L[5]);
            bf16split(av[3].x, av[3].y, H[6], L[6]);
            bf16split(av[3].z, av[3].w, H[7], L[7]);
            if (tid < 128) {
                char* pa = sm + A_HI + aBaseSt;
                char* pl = sm + A_LO + aBaseSt;
                #pragma unroll
                for (int c = 0; c < 4; c++) {
                    *reinterpret_cast<uint2*>(pa + c * 8) = make_uint2(H[c], H[c + 4]);
                    *reinterpret_cast<uint2*>(pl + c * 8) = make_uint2(L[c], L[c + 4]);
                }
            }
        }
        {
            char* ph = sm + B_HI + b0BaseSt;
            char* pl = sm + B_LO + b0BaseSt;
            *reinterpret_cast<uint2*>(ph + 0)  = make_uint2(bh0.x, bh1.x);
            *reinterpret_cast<uint2*>(ph + 8)  = make_uint2(bh0.y, bh1.y);
            *reinterpret_cast<uint2*>(ph + 16) = make_uint2(bh0.z, bh1.z);
            *reinterpret_cast<uint2*>(ph + 24) = make_uint2(bh0.w, bh1.w);
            *reinterpret_cast<uint2*>(pl + 0)  = make_uint2(bl0.x, bl1.x);
            *reinterpret_cast<uint2*>(pl + 8)  = make_uint2(bl0.y, bl1.y);
            *reinterpret_cast<uint2*>(pl + 16) = make_uint2(bl0.z, bl1.z);
            *reinterpret_cast<uint2*>(pl + 24) = make_uint2(bl0.w, bl1.w);
        }
        if (hasT1) {
            char* ph = sm + B_HI + b1BaseSt;
            char* pl = sm + B_LO + b1BaseSt;
            *reinterpret_cast<uint2*>(ph + 0)  = make_uint2(ch0.x, ch1.x);
            *reinterpret_cast<uint2*>(ph + 8)  = make_uint2(ch0.y, ch1.y);
            *reinterpret_cast<uint2*>(ph + 16) = make_uint2(ch0.z, ch1.z);
            *reinterpret_cast<uint2*>(ph + 24) = make_uint2(ch0.w, ch1.w);
            *reinterpret_cast<uint2*>(pl + 0)  = make_uint2(cl0.x, cl1.x);
            *reinterpret_cast<uint2*>(pl + 8)  = make_uint2(cl0.y, cl1.y);
            *reinterpret_cast<uint2*>(pl + 16) = make_uint2(cl0.z, cl1.z);
            *reinterpret_cast<uint2*>(pl + 24) = make_uint2(cl0.w, cl1.w);
        }
    }
    __syncthreads();

    // ---------- main loop ----------
    for (int ck = 0; ck < NCHUNK; ck++) {
        const int s = ck & 1;
        const bool more = (ck + 1 < NCHUNK);

        if (more) {
            const int koff = (ck + 1) * KC;
            av[0] = __ldg((const float4*)(asrc + koff + 0));
            av[1] = __ldg((const float4*)(asrc + koff + 4));
            av[2] = __ldg((const float4*)(asrc + koff + 8));
            av[3] = __ldg((const float4*)(asrc + koff + 12));
            bh0 = __ldg((const uint4*)(bsrcH0 + koff));
            bh1 = __ldg((const uint4*)(bsrcH0 + koff + 8));
            bl0 = __ldg((const uint4*)(bsrcL0 + koff));
            bl1 = __ldg((const uint4*)(bsrcL0 + koff + 8));
            if (hasT1) {
                ch0 = __ldg((const uint4*)(bsrcH1 + koff));
                ch1 = __ldg((const uint4*)(bsrcH1 + koff + 8));
                cl0 = __ldg((const uint4*)(bsrcL1 + koff));
                cl1 = __ldg((const uint4*)(bsrcL1 + koff + 8));
            }
        }

        const char* stg = sm + s * STAGE;
        #pragma unroll
        for (int kb = 0; kb < 2; kb++) {
            const char* pa = stg + A_HI + kb * 2048 + (wm * 4) * 256 + lane * 8;
            const char* pb = stg + B_HI + kb * 7168 + (wn * 7) * 256 + lane * 8;
            uint2 Ah[4], Al[4], Bh[7], Bl[7];
            #pragma unroll
            for (int i = 0; i < 4; i++) {
                Ah[i] = *reinterpret_cast<const uint2*>(pa + i * 256);
                Al[i] = *reinterpret_cast<const uint2*>(pa + (A_LO - A_HI) + i * 256);
            }
            #pragma unroll
            for (int j = 0; j < 7; j++) {
                Bh[j] = *reinterpret_cast<const uint2*>(pb + j * 256);
                Bl[j] = *reinterpret_cast<const uint2*>(pb + (B_LO - B_HI) + j * 256);
            }
            #pragma unroll
            for (int f = 0; f < 2; f++) {
                const uint32_t ah0 = Ah[2 * f].x, ah1 = Ah[2 * f + 1].x;
                const uint32_t ah2 = Ah[2 * f].y, ah3 = Ah[2 * f + 1].y;
                const uint32_t al0 = Al[2 * f].x, al1 = Al[2 * f + 1].x;
                const uint32_t al2 = Al[2 * f].y, al3 = Al[2 * f + 1].y;
                #pragma unroll
                for (int j = 0; j < 7; j++) {
                    mma_bf16(acc[f][j], ah0, ah1, ah2, ah3, Bh[j].x, Bh[j].y);
                    mma_bf16(acc[f][j], ah0, ah1, ah2, ah3, Bl[j].x, Bl[j].y);
                    mma_bf16(acc[f][j], al0, al1, al2, al3, Bh[j].x, Bh[j].y);
                }
            }
        }

        if (more) {
            char* stn = sm + (s ^ 1) * STAGE;
            {
                uint32_t H[8], L[8];
                bf16split(av[0].x, av[0].y, H[0], L[0]);
                bf16split(av[0].z, av[0].w, H[1], L[1]);
                bf16split(av[1].x, av[1].y, H[2], L[2]);
                bf16split(av[1].z, av[1].w, H[3], L[3]);
                bf16split(av[2].x, av[2].y, H[4], L[4]);
                bf16split(av[2].z, av[2].w, H[5], L[5]);
                bf16split(av[3].x, av[3].y, H[6], L[6]);
                bf16split(av[3].z, av[3].w, H[7], L[7]);
                if (tid < 128) {
                    char* pa = stn + A_HI + aBaseSt;
                    char* pl = stn + A_LO + aBaseSt;
                    #pragma unroll
                    for (int c = 0; c < 4; c++) {
                        *reinterpret_cast<uint2*>(pa + c * 8) = make_uint2(H[c], H[c + 4]);
                        *reinterpret_cast<uint2*>(pl + c * 8) = make_uint2(L[c], L[c + 4]);
                    }
                }
            }
            {
                char* ph = stn + B_HI + b0BaseSt;
                char* pl = stn + B_LO + b0BaseSt;
                *reinterpret_cast<uint2*>(ph + 0)  = make_uint2(bh0.x, bh1.x);
                *reinterpret_cast<uint2*>(ph + 8)  = make_uint2(bh0.y, bh1.y);
                *reinterpret_cast<uint2*>(ph + 16) = make_uint2(bh0.z, bh1.z);
                *reinterpret_cast<uint2*>(ph + 24) = make_uint2(bh0.w, bh1.w);
                *reinterpret_cast<uint2*>(pl + 0)  = make_uint2(bl0.x, bl1.x);
                *reinterpret_cast<uint2*>(pl + 8)  = make_uint2(bl0.y, bl1.y);
                *reinterpret_cast<uint2*>(pl + 16) = make_uint2(bl0.z, bl1.z);
                *reinterpret_cast<uint2*>(pl + 24) = make_uint2(bl0.w, bl1.w);
            }
            if (hasT1) {
                char* ph = stn + B_HI + b1BaseSt;
                char* pl = stn + B_LO + b1BaseSt;
                *reinterpret_cast<uint2*>(ph + 0)  = make_uint2(ch0.x, ch1.x);
                *reinterpret_cast<uint2*>(ph + 8)  = make_uint2(ch0.y, ch1.y);
                *reinterpret_cast<uint2*>(ph + 16) = make_uint2(ch0.z, ch1.z);
                *reinterpret_cast<uint2*>(ph + 24) = make_uint2(ch0.w, ch1.w);
                *reinterpret_cast<uint2*>(pl + 0)  = make_uint2(cl0.x, cl1.x);
                *reinterpret_cast<uint2*>(pl + 8)  = make_uint2(cl0.y, cl1.y);
                *reinterpret_cast<uint2*>(pl + 16) = make_uint2(cl0.z, cl1.z);
                *reinterpret_cast<uint2*>(pl + 24) = make_uint2(cl0.w, cl1.w);
            }
        }
        __syncthreads();
    }

    // ---------- epilogue: acc + bias -> g_xp ----------
    const float* sbias = reinterpret_cast<const float*>(sm + BIAS_OFF);
    #pragma unroll
    for (int f = 0; f < 2; f++) {
        const int r0 = m0 + wm * 32 + f * 16 + (lane >> 2);
        #pragma unroll
        for (int j = 0; j < 7; j++) {
            const int n = wn * 56 + j * 8 + (lane & 3) * 2;
            if (n < G3) {
                const float2 bias = *reinterpret_cast<const float2*>(sbias + n);
                float2 o0 = make_float2(acc[f][j][0] + bias.x, acc[f][j][1] + bias.y);
                float2 o1 = make_float2(acc[f][j][2] + bias.x, acc[f][j][3] + bias.y);
                *reinterpret_cast<float2*>(g_xp + (size_t)r0 * G3 + n) = o0;
                *reinterpret_cast<float2*>(g_xp + (size_t)(r0 + 8) * G3 + n) = o1;
            }
        }
    }
}

// ---------------- kernel: GRU (one block per batch, sequential in T) -------
// Proven ~510us version: 256 threads, g<216 matvec (f32x2), threads 0..71
// gates, warp 7 computes q[t-1] overlapped with the matvec.
__global__ void __launch_bounds__(256) gru_kernel(const float* __restrict__ w_hh,
                                                  const float* __restrict__ b_hh,
                                                  const float* __restrict__ w_reg,
                                                  const float* __restrict__ b_reg,
                                                  const int* __restrict__ x_len) {
    __shared__ __align__(16) float hbuf[2][72];
    __shared__ float pre[144];
    __shared__ float hpn[72];
    __shared__ float xnn[72];

    const int b = blockIdx.x;
    const int g = threadIdx.x;
    const int L = x_len[b];

    u64 wl[36];
    float bh = 0.f;
    if (g < G3) {
        bh = b_hh[g];
        const u64* wp = reinterpret_cast<const u64*>(w_hh + g * Hdim);
        #pragma unroll
        for (int k = 0; k < 36; k++) wl[k] = wp[k];
    }
    const int lane = g - 224;
    float wq0 = 0.f, wq1 = 0.f, wq2 = 0.f;
    if (g >= 224 && lane < 24) {
        wq0 = w_reg[3 * lane];
        wq1 = w_reg[3 * lane + 1];
        wq2 = w_reg[3 * lane + 2];
    }
    const float breg = b_reg[0];
    if (g < 72) hbuf[0][g] = 0.f;
    __syncthreads();

    const float* xpb = g_xp + (size_t)b * Tlen * G3;
    float xcur = (g < G3) ? xpb[g] : 0.f;
    int cur = 0;

    for (int t = 0; t < L; t++) {
        float xnxt = 0.f;
        if (g < G3 && t + 1 < Tlen) xnxt = __ldg(xpb + (size_t)(t + 1) * G3 + g);

        if (g < G3) {
            const ulonglong2* hp4 = reinterpret_cast<const ulonglong2*>(hbuf[cur]);
            u64 a0 = 0ULL, a1 = 0ULL, a2 = 0ULL, a3 = 0ULL;
            #pragma unroll
            for (int k = 0; k < 18; k += 2) {
                ulonglong2 h0 = hp4[k];
                ulonglong2 h1 = hp4[k + 1];
                a0 = fma2(h0.x, wl[2 * k], a0);
                a1 = fma2(h0.y, wl[2 * k + 1], a1);
                a2 = fma2(h1.x, wl[2 * k + 2], a2);
                a3 = fma2(h1.y, wl[2 * k + 3], a3);
            }
            float l0, h0f, l1, h1f, l2, h2f, l3, h3f;
            upk2(a0, l0, h0f); upk2(a1, l1, h1f);
            upk2(a2, l2, h2f); upk2(a3, l3, h3f);
            float hp = bh + ((l0 + h0f) + (l1 + h1f)) + ((l2 + h2f) + (l3 + h3f));
            if (g < 144) {
                pre[g] = xcur + hp;
            } else {
                hpn[g - 144] = hp;
                xnn[g - 144] = xcur;
            }
        } else if (g >= 224 && t > 0) {
            float s = 0.f;
            if (lane < 24) {
                s = hbuf[cur][3 * lane] * wq0
                  + hbuf[cur][3 * lane + 1] * wq1
                  + hbuf[cur][3 * lane + 2] * wq2;
            }
            s += __shfl_down_sync(0xffffffffu, s, 16);
            s += __shfl_down_sync(0xffffffffu, s, 8);
            s += __shfl_down_sync(0xffffffffu, s, 4);
            s += __shfl_down_sync(0xffffffffu, s, 2);
            s += __shfl_down_sync(0xffffffffu, s, 1);
            if (lane == 0) g_q[b * Tlen + (t - 1)] = s + breg;
        }
        __syncthreads();

        if (g < 72) {
            float r = sigf(pre[g]);
            float z = sigf(pre[72 + g]);
            float n = tanhfast(xnn[g] + r * hpn[g]);
            hbuf[cur ^ 1][g] = (1.0f - z) * n + z * hbuf[cur][g];
        }
        __syncthreads();

        cur ^= 1;
        xcur = xnxt;
    }

    if (g >= 224) {
        float s = 0.f;
        if (lane < 24) {
            s = hbuf[cur][3 * lane] * wq0
              + hbuf[cur][3 * lane + 1] * wq1
              + hbuf[cur][3 * lane + 2] * wq2;
        }
        s += __shfl_down_sync(0xffffffffu, s, 16);
        s += __shfl_down_sync(0xffffffffu, s, 8);
        s += __shfl_down_sync(0xffffffffu, s, 4);
        s += __shfl_down_sync(0xffffffffu, s, 2);
        s += __shfl_down_sync(0xffffffffu, s, 1);
        if (lane == 0) g_q[b * Tlen + (L - 1)] = s + breg;
    }
    for (int tt = L + g; tt < Tlen; tt += 256) g_q[b * Tlen + tt] = 0.f;
}

// ---------------- kernel: SITP pooling + heads -----------------------------
__global__ void __launch_bounds__(256) pool_kernel(const int* __restrict__ x_len,
                                                   const float* nw1, const float* nb1,
                                                   const float* nw2, const float* nb2,
                                                   const float* lw, const float* lb,
                                                   float* __restrict__ out) {
    __shared__ float qs[Tlen];
    __shared__ float ws[Tlen];
    __shared__ float red[256];
    const int b = blockIdx.x;
    const int tid = threadIdx.x;
    const int L = x_len[b];

    for (int i = tid; i < Tlen; i += 256) {
        float qv = g_q[b * Tlen + i];
        qs[i] = qv;
        ws[i] = (i < L) ? expf(-qv) : 0.f;
    }
    __syncthreads();

    float sum = 0.f;
    for (int t = tid; t < Tlen; t += 256) {
        if (t < L) {
            float xmin = qs[t];
            #pragma unroll
            for (int j = 1; j < TAU; j++) {
                int s = t - j;
                if (s >= 0) xmin = fminf(xmin, qs[s]);
            }
            float num = 0.f, den = 0.f;
            #pragma unroll
            for (int j = 0; j < TAU; j++) {
                int s = t + j;
                if (s < Tlen) { num += ws[s] * qs[s]; den += ws[s]; }
            }
            float y = (den > 0.f) ? num / fmaxf(den, 1e-30f) : 0.f;
            sum += 0.5f * y + 0.5f * xmin;
        }
    }
    red[tid] = sum;
    __syncthreads();
    for (int off = 128; off > 0; off >>= 1) {
        if (tid < off) red[tid] += red[tid + off];
        __syncthreads();
    }
    if (tid == 0) {
        float rel = sigf(red[0] / (float)L);
        float mapped = sigf(nw1[0] * rel + nb1[0]) * nw2[0] + nb2[0];
        float aligned = lw[0] * mapped + lb[0];
        out[b] = rel;
        out[Bsz + b] = mapped;
        out[2 * Bsz + b] = aligned;
    }
}

// ---------------- launch ----------------------------------------------------
extern "C" void kernel_launch(void* const* d_in, const int* in_sizes, int n_in,
                              void* d_out, int out_size) {
    const float* x     = (const float*)d_in[0];
    const int*   x_len = (const int*)  d_in[1];
    const float* w_dr  = (const float*)d_in[2];
    const float* b_dr  = (const float*)d_in[3];
    const float* w_ih  = (const float*)d_in[4];
    const float* w_hh  = (const float*)d_in[5];
    const float* b_ih  = (const float*)d_in[6];
    const float* b_hh  = (const float*)d_in[7];
    const float* w_reg = (const float*)d_in[8];
    const float* b_reg = (const float*)d_in[9];
    const float* nw1   = (const float*)d_in[10];
    const float* nb1   = (const float*)d_in[11];
    const float* nw2   = (const float*)d_in[12];
    const float* nb2   = (const float*)d_in[13];
    const float* lw    = (const float*)d_in[14];
    const float* lb    = (const float*)d_in[15];
    float* out = (float*)d_out;

    cudaFuncSetAttribute(gemm_hmma_kernel,
                         cudaFuncAttributeMaxDynamicSharedMemorySize, GEMM_SMEM);

    bc_kernel<<<1, 256>>>(w_ih, b_dr, b_ih);
    combine_kernel<<<dim3(Din / 64, G3 / 24), 384>>>(w_dr, w_ih);
    gemm_hmma_kernel<<<(Bsz * Tlen) / 64, 256, GEMM_SMEM>>>(x, x_len);
    gru_kernel<<<Bsz, 256>>>(w_hh, b_hh, w_reg, b_reg, x_len);
    pool_kernel<<<Bsz, 256>>>(x_len, nw1, nb1, nw2, nb2, lw, lb, out);
}

// round 9
// speedup vs baseline: 1.1007x; 1.0857x over previous
#include <cuda_runtime.h>
#include <cuda_bf16.h>
#include <math.h>
#include <stdint.h>

// Problem constants
#define Bsz   16
#define Tlen  1024
#define Din   8704
#define Rdim  256
#define Hdim  72
#define G3    216     // 3*H
#define TAU   12

typedef unsigned long long u64;

// ---------------- scratch (device globals; no allocation allowed) ----------
__device__ __nv_bfloat16 g_wchi[(size_t)G3 * Din];  // combined weight hi (bf16)
__device__ __nv_bfloat16 g_wclo[(size_t)G3 * Din];  // combined weight lo (bf16)
__device__ float g_bc[G3];                          // combined bias
__device__ float g_xp[(size_t)Bsz * Tlen * G3];     // pre-GRU activations
__device__ float g_q[Bsz * Tlen];                   // per-frame scores

// ---------------- helpers ---------------------------------------------------
__device__ __forceinline__ void upk2(u64 v, float& lo, float& hi) {
    asm("mov.b64 {%0, %1}, %2;" : "=f"(lo), "=f"(hi) : "l"(v));
}
__device__ __forceinline__ u64 fma2(u64 a, u64 b, u64 c) {
    u64 d;
    asm("fma.rn.f32x2 %0, %1, %2, %3;" : "=l"(d) : "l"(a), "l"(b), "l"(c));
    return d;
}
__device__ __forceinline__ float sigf(float v) {
    return __fdividef(1.0f, 1.0f + __expf(-v));
}
__device__ __forceinline__ float tanhfast(float v) {
    return 1.0f - __fdividef(2.0f, __expf(2.0f * v) + 1.0f);
}
// split a,b (fp32) into packed bf16x2 hi + lo:  lower16 <- a, upper16 <- b
__device__ __forceinline__ void bf16split(float a, float b, uint32_t& hp, uint32_t& lp) {
    asm("cvt.rn.bf16x2.f32 %0, %1, %2;" : "=r"(hp) : "f"(b), "f"(a));
    float ha = __uint_as_float(hp << 16);
    float hb = __uint_as_float(hp & 0xffff0000u);
    float ra = a - ha, rb = b - hb;
    asm("cvt.rn.bf16x2.f32 %0, %1, %2;" : "=r"(lp) : "f"(rb), "f"(ra));
}
// m16n8k16 bf16 MMA (sm_80+ PTX, no arch-feature suffix needed)
__device__ __forceinline__ void mma_bf16(float* d, uint32_t a0, uint32_t a1,
                                         uint32_t a2, uint32_t a3,
                                         uint32_t b0, uint32_t b1) {
    asm volatile(
        "mma.sync.aligned.m16n8k16.row.col.f32.bf16.bf16.f32 "
        "{%0,%1,%2,%3}, {%4,%5,%6,%7}, {%8,%9}, {%0,%1,%2,%3};"
        : "+f"(d[0]), "+f"(d[1]), "+f"(d[2]), "+f"(d[3])
        : "r"(a0), "r"(a1), "r"(a2), "r"(a3), "r"(b0), "r"(b1));
}
__device__ __forceinline__ uint32_t smem_u32(const void* p) {
    uint32_t a;
    asm("{ .reg .u64 t; cvta.to.shared.u64 t, %1; cvt.u32.u64 %0, t; }" : "=r"(a) : "l"(p));
    return a;
}
__device__ __forceinline__ void cp_async16(uint32_t dst, const void* src) {
    asm volatile("cp.async.cg.shared.global [%0], [%1], 16;" :: "r"(dst), "l"(src));
}
#define CP_COMMIT()  asm volatile("cp.async.commit_group;" ::: "memory")
#define CP_WAIT1()   asm volatile("cp.async.wait_group 1;" ::: "memory")
#define CP_WAIT0()   asm volatile("cp.async.wait_group 0;" ::: "memory")

// ---------------- kernel: combined bias b_c = w_ih @ b_dr + b_ih -----------
__global__ void bc_kernel(const float* __restrict__ w_ih,
                          const float* __restrict__ b_dr,
                          const float* __restrict__ b_ih) {
    int g = threadIdx.x;
    if (g >= G3) return;
    float acc = b_ih[g];
    for (int r = 0; r < Rdim; r++) acc += w_ih[g * Rdim + r] * b_dr[r];
    g_bc[g] = acc;
}

// ---------------- kernel: combined weight, split to bf16 hi/lo -------------
// grid (8704/64, 216/24), block 384
__global__ void __launch_bounds__(384) combine_kernel(const float* __restrict__ w_dr,
                                                      const float* __restrict__ w_ih) {
    __shared__ float sWdr[128][64];
    __shared__ float sWih[24][128];
    const int d0 = blockIdx.x * 64;
    const int g0 = blockIdx.y * 24;
    const int tid = threadIdx.x;
    const int dloc = (tid & 15) * 4;
    const int gloc = tid >> 4;

    float a0 = 0.f, a1 = 0.f, a2 = 0.f, a3 = 0.f;

    for (int r0 = 0; r0 < Rdim; r0 += 128) {
        for (int idx = tid; idx < 128 * 64; idx += 384) {
            int r = idx >> 6, d = idx & 63;
            sWdr[r][d] = w_dr[(size_t)(r0 + r) * Din + d0 + d];
        }
        for (int idx = tid; idx < 24 * 128; idx += 384) {
            int g = idx >> 7, r = idx & 127;
            sWih[g][r] = w_ih[(g0 + g) * Rdim + r0 + r];
        }
        __syncthreads();
        #pragma unroll 4
        for (int r = 0; r < 128; r++) {
            float wi = sWih[gloc][r];
            float4 wd = *reinterpret_cast<const float4*>(&sWdr[r][dloc]);
            a0 = fmaf(wi, wd.x, a0);
            a1 = fmaf(wi, wd.y, a1);
            a2 = fmaf(wi, wd.z, a2);
            a3 = fmaf(wi, wd.w, a3);
        }
        __syncthreads();
    }
    uint32_t h01, l01, h23, l23;
    bf16split(a0, a1, h01, l01);
    bf16split(a2, a3, h23, l23);
    const size_t e = (size_t)(g0 + gloc) * Din + d0 + dloc;
    *reinterpret_cast<uint2*>(reinterpret_cast<char*>(g_wchi) + e * 2) = make_uint2(h01, h23);
    *reinterpret_cast<uint2*>(reinterpret_cast<char*>(g_wclo) + e * 2) = make_uint2(l01, l23);
}

// ---------------- kernel: HMMA GEMM  xp = x @ w_c^T + b_c ------------------
// R5 (measured-best) structure with KC 32->64: barriers & per-chunk fixed
// costs halved. A: register-staged fp32->bf16 split, 2 stages, fragment-
// packed. B: cp.async raw bf16 (pre-split), 3-stage ring, rows padded to
// 144B (conflict-free LDS.32 fragment loads). 3 passes hi*hi+hi*lo+lo*hi.
#define KC       64
#define NCHUNK   (Din / KC)      // 136
#define A_ST_SZ  16384           // hi 8192 + lo 8192
#define A_LO_OFF 8192
#define B_BASE   32768
#define B_ROW    144
#define B_LO_OFF 32256           // 224 * 144
#define B_ST_SZ  64512           // hi 32256 + lo 32256
#define BIAS_OFF2 (B_BASE + 3 * B_ST_SZ)        // 226304
#define GEMM_SMEM (BIAS_OFF2 + 896)             // 227200

__global__ void __launch_bounds__(256, 1) gemm_hmma_kernel(const float* __restrict__ x,
                                                           const int* __restrict__ x_len) {
    extern __shared__ __align__(16) char sm[];
    const int tid = threadIdx.x;
    const int bx = blockIdx.x;
    const int batch = bx & 15;
    const int tile = bx >> 4;
    const int m0 = batch * Tlen + tile * 64;
    if (tile * 64 >= x_len[batch]) return;   // tile fully beyond x_len

    const uint32_t sb = smem_u32(sm);

    // bias to smem
    if (tid < G3) *reinterpret_cast<float*>(sm + BIAS_OFF2 + tid * 4) = g_bc[tid];

    // ---- A writer role: row ar = tid>>2, k-quarter q = tid&3 (16 fp32) ----
    const int ar = tid >> 2, aq = tid & 3;
    const float* asrc = x + (size_t)(m0 + ar) * Din + aq * 16;
    const uint32_t aSt = (uint32_t)(aq * 2048 + (ar >> 3) * 256 + (ar & 7) * 32);

    // ---- B cp.async role: 14 tasks/thread ----
    // task = half(0..1) x row(0..223) x seg(0..7, 16B each of the 128B row)
    uint32_t bDst[14];
    const char* bSrc[14];
    #pragma unroll
    for (int i = 0; i < 14; i++) {
        const int task = tid + i * 256;       // 0..3583
        const int hl = task / 1792;
        const int rem = task - hl * 1792;
        const int row = rem >> 3, seg = rem & 7;
        const int rs = (row < G3) ? row : (G3 - 1);
        bDst[i] = sb + B_BASE + (uint32_t)(hl * B_LO_OFF + row * B_ROW + seg * 16);
        const char* base = hl ? (const char*)g_wclo : (const char*)g_wchi;
        bSrc[i] = base + (size_t)rs * (Din * 2) + seg * 16;
    }

    // ---- compute roles ----
    const int wid = tid >> 5;
    const int lane = tid & 31;
    const int wm = wid >> 2;          // 0..1
    const int wn = wid & 3;           // 0..3

    float acc[2][7][4];
    #pragma unroll
    for (int f = 0; f < 2; f++)
        #pragma unroll
        for (int j = 0; j < 7; j++)
            #pragma unroll
            for (int c = 0; c < 4; c++) acc[f][j][c] = 0.f;

    float4 av[4];

    #define STORE_A(dstbase) do {                                               \
        uint32_t H[8], L[8];                                                    \
        bf16split(av[0].x, av[0].y, H[0], L[0]);                                \
        bf16split(av[0].z, av[0].w, H[1], L[1]);                                \
        bf16split(av[1].x, av[1].y, H[2], L[2]);                                \
        bf16split(av[1].z, av[1].w, H[3], L[3]);                                \
        bf16split(av[2].x, av[2].y, H[4], L[4]);                                \
        bf16split(av[2].z, av[2].w, H[5], L[5]);                                \
        bf16split(av[3].x, av[3].y, H[6], L[6]);                                \
        bf16split(av[3].z, av[3].w, H[7], L[7]);                                \
        char* pa = (dstbase) + aSt;                                             \
        char* pl = pa + A_LO_OFF;                                               \
        _Pragma("unroll")                                                       \
        for (int c = 0; c < 4; c++) {                                           \
            *reinterpret_cast<uint2*>(pa + c * 8) = make_uint2(H[c], H[c + 4]); \
            *reinterpret_cast<uint2*>(pl + c * 8) = make_uint2(L[c], L[c + 4]); \
        }                                                                       \
    } while (0)

    // ---------- prologue ----------
    // B chunks 0 and 1 via cp.async
    #pragma unroll
    for (int i = 0; i < 14; i++) cp_async16(bDst[i], bSrc[i]);
    CP_COMMIT();
    #pragma unroll
    for (int i = 0; i < 14; i++) cp_async16(bDst[i] + B_ST_SZ, bSrc[i] + 128);
    CP_COMMIT();
    // A chunk 0: load, split, store
    {
        av[0] = __ldg((const float4*)(asrc + 0));
        av[1] = __ldg((const float4*)(asrc + 4));
        av[2] = __ldg((const float4*)(asrc + 8));
        av[3] = __ldg((const float4*)(asrc + 12));
        STORE_A(sm);
    }
    CP_WAIT1();         // B0 complete (B1 may pend)
    __syncthreads();

    // ---------- main loop ----------
    for (int ck = 0; ck < NCHUNK; ck++) {
        const int sA = ck & 1;
        const int sB = ck % 3;
        const bool more = (ck + 1 < NCHUNK);
        const bool more2 = (ck + 2 < NCHUNK);

        // issue B chunk ck+2 (into the stage consumed last iteration)
        if (more2) {
            const int sB2 = (ck + 2) % 3;
            const size_t go = (size_t)(ck + 2) * 128;
            #pragma unroll
            for (int i = 0; i < 14; i++)
                cp_async16(bDst[i] + (uint32_t)(sB2 * B_ST_SZ), bSrc[i] + go);
            CP_COMMIT();
        }
        // issue A loads for chunk ck+1
        if (more) {
            const int koff = (ck + 1) * KC;
            av[0] = __ldg((const float4*)(asrc + koff + 0));
            av[1] = __ldg((const float4*)(asrc + koff + 4));
            av[2] = __ldg((const float4*)(asrc + koff + 8));
            av[3] = __ldg((const float4*)(asrc + koff + 12));
        }

        // compute on (A stage sA, B stage sB)
        const char* ast = sm + sA * A_ST_SZ;
        const char* bst = sm + B_BASE + sB * B_ST_SZ;
        #pragma unroll
        for (int kb = 0; kb < 4; kb++) {
            const char* pa = ast + kb * 2048 + wm * 1024 + lane * 8;
            uint2 Ah[4], Al[4];
            #pragma unroll
            for (int i = 0; i < 4; i++) {
                Ah[i] = *reinterpret_cast<const uint2*>(pa + i * 256);
                Al[i] = *reinterpret_cast<const uint2*>(pa + A_LO_OFF + i * 256);
            }
            uint32_t Bh0[7], Bh1[7], Bl0[7], Bl1[7];
            #pragma unroll
            for (int j = 0; j < 7; j++) {
                const uint32_t bro = (uint32_t)((wn * 56 + j * 8 + (lane >> 2)) * B_ROW
                                                + kb * 32 + (lane & 3) * 4);
                Bh0[j] = *reinterpret_cast<const uint32_t*>(bst + bro);
                Bh1[j] = *reinterpret_cast<const uint32_t*>(bst + bro + 16);
                Bl0[j] = *reinterpret_cast<const uint32_t*>(bst + B_LO_OFF + bro);
                Bl1[j] = *reinterpret_cast<const uint32_t*>(bst + B_LO_OFF + bro + 16);
            }
            #pragma unroll
            for (int f = 0; f < 2; f++) {
                const uint32_t ah0 = Ah[2 * f].x, ah1 = Ah[2 * f + 1].x;
                const uint32_t ah2 = Ah[2 * f].y, ah3 = Ah[2 * f + 1].y;
                const uint32_t al0 = Al[2 * f].x, al1 = Al[2 * f + 1].x;
                const uint32_t al2 = Al[2 * f].y, al3 = Al[2 * f + 1].y;
                #pragma unroll
                for (int j = 0; j < 7; j++) {
                    mma_bf16(acc[f][j], ah0, ah1, ah2, ah3, Bh0[j], Bh1[j]);
                    mma_bf16(acc[f][j], ah0, ah1, ah2, ah3, Bl0[j], Bl1[j]);
                    mma_bf16(acc[f][j], al0, al1, al2, al3, Bh0[j], Bh1[j]);
                }
            }
        }

        // store A chunk ck+1 into stage sA^1
        if (more) {
            STORE_A(sm + (sA ^ 1) * A_ST_SZ);
        }
        // ensure B chunk ck+1 landed before the barrier
        if (more2) { CP_WAIT1(); } else { CP_WAIT0(); }
        __syncthreads();
    }

    // ---------- epilogue: acc + bias -> g_xp ----------
    const float* sbias = reinterpret_cast<const float*>(sm + BIAS_OFF2);
    #pragma unroll
    for (int f = 0; f < 2; f++) {
        const int r0 = m0 + wm * 32 + f * 16 + (lane >> 2);
        #pragma unroll
        for (int j = 0; j < 7; j++) {
            const int n = wn * 56 + j * 8 + (lane & 3) * 2;
            if (n < G3) {
                const float2 bias = *reinterpret_cast<const float2*>(sbias + n);
                float2 o0 = make_float2(acc[f][j][0] + bias.x, acc[f][j][1] + bias.y);
                float2 o1 = make_float2(acc[f][j][2] + bias.x, acc[f][j][3] + bias.y);
                *reinterpret_cast<float2*>(g_xp + (size_t)r0 * G3 + n) = o0;
                *reinterpret_cast<float2*>(g_xp + (size_t)(r0 + 8) * G3 + n) = o1;
            }
        }
    }
    #undef STORE_A
}

// ---------------- kernel: GRU (one block per batch, sequential in T) -------
// Proven ~510us version: 256 threads, g<216 matvec (f32x2), threads 0..71
// gates, warp 7 computes q[t-1] overlapped with the matvec.
__global__ void __launch_bounds__(256) gru_kernel(const float* __restrict__ w_hh,
                                                  const float* __restrict__ b_hh,
                                                  const float* __restrict__ w_reg,
                                                  const float* __restrict__ b_reg,
                                                  const int* __restrict__ x_len) {
    __shared__ __align__(16) float hbuf[2][72];
    __shared__ float pre[144];
    __shared__ float hpn[72];
    __shared__ float xnn[72];

    const int b = blockIdx.x;
    const int g = threadIdx.x;
    const int L = x_len[b];

    u64 wl[36];
    float bh = 0.f;
    if (g < G3) {
        bh = b_hh[g];
        const u64* wp = reinterpret_cast<const u64*>(w_hh + g * Hdim);
        #pragma unroll
        for (int k = 0; k < 36; k++) wl[k] = wp[k];
    }
    const int lane = g - 224;
    float wq0 = 0.f, wq1 = 0.f, wq2 = 0.f;
    if (g >= 224 && lane < 24) {
        wq0 = w_reg[3 * lane];
        wq1 = w_reg[3 * lane + 1];
        wq2 = w_reg[3 * lane + 2];
    }
    const float breg = b_reg[0];
    if (g < 72) hbuf[0][g] = 0.f;
    __syncthreads();

    const float* xpb = g_xp + (size_t)b * Tlen * G3;
    float xcur = (g < G3) ? xpb[g] : 0.f;
    int cur = 0;

    for (int t = 0; t < L; t++) {
        float xnxt = 0.f;
        if (g < G3 && t + 1 < Tlen) xnxt = __ldg(xpb + (size_t)(t + 1) * G3 + g);

        if (g < G3) {
            const ulonglong2* hp4 = reinterpret_cast<const ulonglong2*>(hbuf[cur]);
            u64 a0 = 0ULL, a1 = 0ULL, a2 = 0ULL, a3 = 0ULL;
            #pragma unroll
            for (int k = 0; k < 18; k += 2) {
                ulonglong2 h0 = hp4[k];
                ulonglong2 h1 = hp4[k + 1];
                a0 = fma2(h0.x, wl[2 * k], a0);
                a1 = fma2(h0.y, wl[2 * k + 1], a1);
                a2 = fma2(h1.x, wl[2 * k + 2], a2);
                a3 = fma2(h1.y, wl[2 * k + 3], a3);
            }
            float l0, h0f, l1, h1f, l2, h2f, l3, h3f;
            upk2(a0, l0, h0f); upk2(a1, l1, h1f);
            upk2(a2, l2, h2f); upk2(a3, l3, h3f);
            float hp = bh + ((l0 + h0f) + (l1 + h1f)) + ((l2 + h2f) + (l3 + h3f));
            if (g < 144) {
                pre[g] = xcur + hp;
            } else {
                hpn[g - 144] = hp;
                xnn[g - 144] = xcur;
            }
        } else if (g >= 224 && t > 0) {
            float s = 0.f;
            if (lane < 24) {
                s = hbuf[cur][3 * lane] * wq0
                  + hbuf[cur][3 * lane + 1] * wq1
                  + hbuf[cur][3 * lane + 2] * wq2;
            }
            s += __shfl_down_sync(0xffffffffu, s, 16);
            s += __shfl_down_sync(0xffffffffu, s, 8);
            s += __shfl_down_sync(0xffffffffu, s, 4);
            s += __shfl_down_sync(0xffffffffu, s, 2);
            s += __shfl_down_sync(0xffffffffu, s, 1);
            if (lane == 0) g_q[b * Tlen + (t - 1)] = s + breg;
        }
        __syncthreads();

        if (g < 72) {
            float r = sigf(pre[g]);
            float z = sigf(pre[72 + g]);
            float n = tanhfast(xnn[g] + r * hpn[g]);
            hbuf[cur ^ 1][g] = (1.0f - z) * n + z * hbuf[cur][g];
        }
        __syncthreads();

        cur ^= 1;
        xcur = xnxt;
    }

    if (g >= 224) {
        float s = 0.f;
        if (lane < 24) {
            s = hbuf[cur][3 * lane] * wq0
              + hbuf[cur][3 * lane + 1] * wq1
              + hbuf[cur][3 * lane + 2] * wq2;
        }
        s += __shfl_down_sync(0xffffffffu, s, 16);
        s += __shfl_down_sync(0xffffffffu, s, 8);
        s += __shfl_down_sync(0xffffffffu, s, 4);
        s += __shfl_down_sync(0xffffffffu, s, 2);
        s += __shfl_down_sync(0xffffffffu, s, 1);
        if (lane == 0) g_q[b * Tlen + (L - 1)] = s + breg;
    }
    for (int tt = L + g; tt < Tlen; tt += 256) g_q[b * Tlen + tt] = 0.f;
}

// ---------------- kernel: SITP pooling + heads -----------------------------
__global__ void __launch_bounds__(256) pool_kernel(const int* __restrict__ x_len,
                                                   const float* nw1, const float* nb1,
                                                   const float* nw2, const float* nb2,
                                                   const float* lw, const float* lb,
                                                   float* __restrict__ out) {
    __shared__ float qs[Tlen];
    __shared__ float ws[Tlen];
    __shared__ float red[256];
    const int b = blockIdx.x;
    const int tid = threadIdx.x;
    const int L = x_len[b];

    for (int i = tid; i < Tlen; i += 256) {
        float qv = g_q[b * Tlen + i];
        qs[i] = qv;
        ws[i] = (i < L) ? expf(-qv) : 0.f;
    }
    __syncthreads();

    float sum = 0.f;
    for (int t = tid; t < Tlen; t += 256) {
        if (t < L) {
            float xmin = qs[t];
            #pragma unroll
            for (int j = 1; j < TAU; j++) {
                int s = t - j;
                if (s >= 0) xmin = fminf(xmin, qs[s]);
            }
            float num = 0.f, den = 0.f;
            #pragma unroll
            for (int j = 0; j < TAU; j++) {
                int s = t + j;
                if (s < Tlen) { num += ws[s] * qs[s]; den += ws[s]; }
            }
            float y = (den > 0.f) ? num / fmaxf(den, 1e-30f) : 0.f;
            sum += 0.5f * y + 0.5f * xmin;
        }
    }
    red[tid] = sum;
    __syncthreads();
    for (int off = 128; off > 0; off >>= 1) {
        if (tid < off) red[tid] += red[tid + off];
        __syncthreads();
    }
    if (tid == 0) {
        float rel = sigf(red[0] / (float)L);
        float mapped = sigf(nw1[0] * rel + nb1[0]) * nw2[0] + nb2[0];
        float aligned = lw[0] * mapped + lb[0];
        out[b] = rel;
        out[Bsz + b] = mapped;
        out[2 * Bsz + b] = aligned;
    }
}

// ---------------- launch ----------------------------------------------------
extern "C" void kernel_launch(void* const* d_in, const int* in_sizes, int n_in,
                              void* d_out, int out_size) {
    const float* x     = (const float*)d_in[0];
    const int*   x_len = (const int*)  d_in[1];
    const float* w_dr  = (const float*)d_in[2];
    const float* b_dr  = (const float*)d_in[3];
    const float* w_ih  = (const float*)d_in[4];
    const float* w_hh  = (const float*)d_in[5];
    const float* b_ih  = (const float*)d_in[6];
    const float* b_hh  = (const float*)d_in[7];
    const float* w_reg = (const float*)d_in[8];
    const float* b_reg = (const float*)d_in[9];
    const float* nw1   = (const float*)d_in[10];
    const float* nb1   = (const float*)d_in[11];
    const float* nw2   = (const float*)d_in[12];
    const float* nb2   = (const float*)d_in[13];
    const float* lw    = (const float*)d_in[14];
    const float* lb    = (const float*)d_in[15];
    float* out = (float*)d_out;

    cudaFuncSetAttribute(gemm_hmma_kernel,
                         cudaFuncAttributeMaxDynamicSharedMemorySize, GEMM_SMEM);

    bc_kernel<<<1, 256>>>(w_ih, b_dr, b_ih);
    combine_kernel<<<dim3(Din / 64, G3 / 24), 384>>>(w_dr, w_ih);
    gemm_hmma_kernel<<<(Bsz * Tlen) / 64, 256, GEMM_SMEM>>>(x, x_len);
    gru_kernel<<<Bsz, 256>>>(w_hh, b_hh, w_reg, b_reg, x_len);
    pool_kernel<<<Bsz, 256>>>(x_len, nw1, nb1, nw2, nb2, lw, lb, out);
}